// round 14
// baseline (speedup 1.0000x reference)
#include <cuda_runtime.h>
#include <cuda_bf16.h>
#include <math.h>

#define SEQ 4096
#define DIM 1024
#define NH  16
#define HD  64
#define KT  32   // keys per flash tile

// ---------------- device scratch (no allocation allowed) ----------------
__device__ float g_qkv[SEQ * 3 * DIM];      // QKV projection output (fp32)
__device__ float g_Q[NH * SEQ * HD];        // roped Q, head-major, fp32
__device__ uint4 g_Kh4[NH * SEQ * HD / 8];  // K bf16 hi, head-major
__device__ uint4 g_Kl4[NH * SEQ * HD / 8];  // K bf16 lo
__device__ uint4 g_Vh4[NH * SEQ * HD / 8];  // V bf16 hi
__device__ uint4 g_Vl4[NH * SEQ * HD / 8];  // V bf16 lo
__device__ unsigned g_xh[SEQ * DIM / 2];    // x split, row-major kpair words
__device__ unsigned g_xl[SEQ * DIM / 2];
__device__ unsigned g_Wqh[(DIM / 2) * (3 * DIM)];  // Wqkv split, kpair-packed
__device__ unsigned g_Wql[(DIM / 2) * (3 * DIM)];
__device__ unsigned g_Woh[(DIM / 2) * DIM];        // Wo split, kpair-packed
__device__ unsigned g_Wol[(DIM / 2) * DIM];
__device__ unsigned g_Oh[SEQ * DIM / 2];    // attention out split, row-major
__device__ unsigned g_Ol[SEQ * DIM / 2];
__device__ float g_att[SEQ * DIM];          // after out-proj, pre-LN
__device__ float g_cos[SEQ * 512];
__device__ float g_sin[SEQ * 512];
__device__ float g_invf[512];

// ---------------- BF16 helpers ------------------------------------------
__device__ __forceinline__ void mma_bf16(float* c, const unsigned* a, const unsigned* b) {
    asm volatile(
        "mma.sync.aligned.m16n8k16.row.col.f32.bf16.bf16.f32 "
        "{%0,%1,%2,%3}, {%4,%5,%6,%7}, {%8,%9}, {%0,%1,%2,%3};"
        : "+f"(c[0]), "+f"(c[1]), "+f"(c[2]), "+f"(c[3])
        : "r"(a[0]), "r"(a[1]), "r"(a[2]), "r"(a[3]), "r"(b[0]), "r"(b[1]));
}
__device__ __forceinline__ void split_pack(float a, float b, unsigned& h, unsigned& l) {
    __nv_bfloat16 ah = __float2bfloat16_rn(a);
    __nv_bfloat16 bh = __float2bfloat16_rn(b);
    float ar = a - __bfloat162float(ah);
    float br = b - __bfloat162float(bh);
    __nv_bfloat162 hv; hv.x = ah; hv.y = bh;
    __nv_bfloat162 lv = __floats2bfloat162_rn(ar, br);
    h = *reinterpret_cast<unsigned*>(&hv);
    l = *reinterpret_cast<unsigned*>(&lv);
}
__device__ __forceinline__ void ldsm_x4_trans(unsigned& r0, unsigned& r1,
                                              unsigned& r2, unsigned& r3, unsigned addr) {
    asm volatile("ldmatrix.sync.aligned.m8n8.x4.trans.shared.b16 {%0,%1,%2,%3}, [%4];"
                 : "=r"(r0), "=r"(r1), "=r"(r2), "=r"(r3) : "r"(addr));
}
__device__ __forceinline__ void ldsm_x4(unsigned& r0, unsigned& r1,
                                        unsigned& r2, unsigned& r3, unsigned addr) {
    asm volatile("ldmatrix.sync.aligned.m8n8.x4.shared.b16 {%0,%1,%2,%3}, [%4];"
                 : "=r"(r0), "=r"(r1), "=r"(r2), "=r"(r3) : "r"(addr));
}
__device__ __forceinline__ unsigned smem_u32(const void* p) {
    unsigned a;
    asm("{ .reg .u64 t; cvta.to.shared.u64 t, %1; cvt.u32.u64 %0, t; }" : "=r"(a) : "l"(p));
    return a;
}
__device__ __forceinline__ void cp16(unsigned saddr, const void* g) {
    asm volatile("cp.async.ca.shared.global [%0], [%1], 16;" :: "r"(saddr), "l"(g));
}
#define CP_COMMIT() asm volatile("cp.async.commit_group;" ::: "memory")
#define CP_WAIT(n)  asm volatile("cp.async.wait_group %0;" :: "n"(n) : "memory")

// ---------------- operand pre-split kernels ------------------------------
// x: row-major fp32 [M][1024] -> row-major kpair words [M][512]
__global__ void split_x_kernel(const float* __restrict__ x) {
    int idx = blockIdx.x * blockDim.x + threadIdx.x;   // SEQ*512
    float2 v = ((const float2*)x)[idx];
    split_pack(v.x, v.y, g_xh[idx], g_xl[idx]);
}
// W: [1024][N] fp32 -> kpair-packed [512][N]: word(kp,n) = {W[2kp][n], W[2kp+1][n]}
__global__ void split_w_kernel(const float* __restrict__ W, unsigned* __restrict__ wh,
                               unsigned* __restrict__ wl, int N) {
    int idx = blockIdx.x * blockDim.x + threadIdx.x;   // 512*N
    int kp = idx / N, n = idx - kp * N;
    float a = W[(size_t)(2 * kp) * N + n];
    float b = W[(size_t)(2 * kp + 1) * N + n];
    split_pack(a, b, wh[idx], wl[idx]);
}

// ---------------- RoPE tables -------------------------------------------
__global__ void rope_invf_kernel() {
    int i = blockIdx.x * blockDim.x + threadIdx.x;
    if (i < 512)
        g_invf[i] = (float)exp(-((double)i) * (9.210340371976184 / 512.0));
}
__global__ void rope_tables_kernel() {
    int idx = blockIdx.x * blockDim.x + threadIdx.x;
    if (idx >= SEQ * 512) return;
    int s = idx >> 9;
    int i = idx & 511;
    float ang = (float)s * g_invf[i];
    double a = (double)ang;
    double k = rint(a * 0.15915494309189535);
    float r = (float)(a - k * 6.283185307179586);
    g_cos[idx] = cosf(r);
    g_sin[idx] = sinf(r);
}

// ---------------- RoPE apply + head-major scatter + bf16 hi/lo split ----
__global__ void rope_scatter_kernel() {
    int idx = blockIdx.x * blockDim.x + threadIdx.x;   // SEQ*DIM threads
    int s = idx >> 10;
    int j = idx & 1023;
    int i = j & 511;
    float c  = g_cos[(s << 9) + i];
    float sn = g_sin[(s << 9) + i];
    const float* row = g_qkv + (size_t)s * (3 * DIM);
    float q = row[j];
    float k = row[DIM + j];
    float v = row[2 * DIM + j];
    float q2, k2;
    if (j < 512) { q2 = -row[j + 512];       k2 = -row[DIM + j + 512]; }
    else         { q2 =  row[j - 512];       k2 =  row[DIM + j - 512]; }
    float qo = q * c + q2 * sn;
    float ko = k * c + k2 * sn;
    int h = j >> 6, d = j & 63;
    int o = ((h * SEQ) + s) * HD + d;
    g_Q[o] = qo;
    __nv_bfloat16 kh = __float2bfloat16_rn(ko);
    ((__nv_bfloat16*)g_Kh4)[o] = kh;
    ((__nv_bfloat16*)g_Kl4)[o] = __float2bfloat16_rn(ko - __bfloat162float(kh));
    __nv_bfloat16 vh = __float2bfloat16_rn(v);
    ((__nv_bfloat16*)g_Vh4)[o] = vh;
    ((__nv_bfloat16*)g_Vl4)[o] = __float2bfloat16_rn(v - __bfloat162float(vh));
}

// ---------------- BF16x3 GEMM on pre-split operands, cp.async pipeline --
// 128x128x32 tile, 2-stage double buffer, pure-copy fills.
// smem word layout: Ash[2][128][20] | Asl | Bsh[2][16][136] | Bsl
#define ASH_OFF 0
#define ASL_OFF 5120
#define BSH_OFF 10240
#define BSL_OFF 14592
#define GEMM_SMEM_BYTES ((14592 + 4352) * 4)

__device__ __forceinline__
void bf16pp_gemm_body(int N,
                      const unsigned* __restrict__ Ah, const unsigned* __restrict__ Al,
                      const unsigned* __restrict__ Bh, const unsigned* __restrict__ Bl,
                      const float* __restrict__ bias, float* __restrict__ C) {
    extern __shared__ unsigned sm[];
    const int KW = DIM / 2;   // 512 kpair words per A row
    int tid = threadIdx.x;
    int w = tid >> 5, lane = tid & 31;
    int g = lane >> 2, c = lane & 3;
    int m0 = blockIdx.y * 128, n0 = blockIdx.x * 128;
    int wm = w >> 1, wn = w & 1;

    int am = tid >> 1, akp = (tid & 1) * 8;   // A fill: row, kpair offset
    int bkp = tid >> 4, bn8 = (tid & 15) * 8; // B fill: kpair row, n offset

    unsigned a_s0 = smem_u32(&sm[ASH_OFF + am * 20 + akp]);
    unsigned a_s1 = smem_u32(&sm[ASL_OFF + am * 20 + akp]);
    unsigned b_s0 = smem_u32(&sm[BSH_OFF + bkp * 136 + bn8]);
    unsigned b_s1 = smem_u32(&sm[BSL_OFF + bkp * 136 + bn8]);
    const unsigned* Agh = Ah + (size_t)(m0 + am) * KW + akp;
    const unsigned* Agl = Al + (size_t)(m0 + am) * KW + akp;
    const unsigned* Bgh = Bh + (size_t)bkp * N + n0 + bn8;
    const unsigned* Bgl = Bl + (size_t)bkp * N + n0 + bn8;

    float acc[2][8][4];
#pragma unroll
    for (int mi = 0; mi < 2; mi++)
#pragma unroll
        for (int ni = 0; ni < 8; ni++)
#pragma unroll
            for (int i = 0; i < 4; i++) acc[mi][ni][i] = 0.f;

    // fill chunk cc into stage st
    auto fill = [&](int cc, int st) {
        unsigned ao = st * 2560 * 4, bo = st * 2176 * 4;
        const unsigned* agh = Agh + cc * 16;
        const unsigned* agl = Agl + cc * 16;
        cp16(a_s0 + ao, agh);      cp16(a_s0 + ao + 16, agh + 4);
        cp16(a_s1 + ao, agl);      cp16(a_s1 + ao + 16, agl + 4);
        const unsigned* bgh = Bgh + (size_t)cc * 16 * N;
        const unsigned* bgl = Bgl + (size_t)cc * 16 * N;
        cp16(b_s0 + bo, bgh);      cp16(b_s0 + bo + 16, bgh + 4);
        cp16(b_s1 + bo, bgl);      cp16(b_s1 + bo + 16, bgl + 4);
    };

    fill(0, 0);
    CP_COMMIT();

    for (int cc = 0; cc < 32; cc++) {
        int st = cc & 1;
        if (cc + 1 < 32) {
            fill(cc + 1, st ^ 1);
            CP_COMMIT();
            CP_WAIT(1);
        } else {
            CP_WAIT(0);
        }
        __syncthreads();

        const unsigned* Ash = sm + ASH_OFF + st * 2560;
        const unsigned* Asl = sm + ASL_OFF + st * 2560;
        const unsigned* Bsh = sm + BSH_OFF + st * 2176;
        const unsigned* Bsl = sm + BSL_OFF + st * 2176;
#pragma unroll
        for (int kk = 0; kk < 2; kk++) {
            unsigned ah[2][4], al[2][4];
#pragma unroll
            for (int mi = 0; mi < 2; mi++) {
                int rb = wm * 32 + mi * 16;
                ah[mi][0] = Ash[(rb + g) * 20 + kk * 8 + c];
                ah[mi][1] = Ash[(rb + g + 8) * 20 + kk * 8 + c];
                ah[mi][2] = Ash[(rb + g) * 20 + kk * 8 + c + 4];
                ah[mi][3] = Ash[(rb + g + 8) * 20 + kk * 8 + c + 4];
                al[mi][0] = Asl[(rb + g) * 20 + kk * 8 + c];
                al[mi][1] = Asl[(rb + g + 8) * 20 + kk * 8 + c];
                al[mi][2] = Asl[(rb + g) * 20 + kk * 8 + c + 4];
                al[mi][3] = Asl[(rb + g + 8) * 20 + kk * 8 + c + 4];
            }
#pragma unroll
            for (int ni = 0; ni < 8; ni++) {
                int nb = wn * 64 + ni * 8 + g;
                unsigned bh[2], bl[2];
                bh[0] = Bsh[(kk * 8 + c) * 136 + nb];
                bh[1] = Bsh[(kk * 8 + c + 4) * 136 + nb];
                bl[0] = Bsl[(kk * 8 + c) * 136 + nb];
                bl[1] = Bsl[(kk * 8 + c + 4) * 136 + nb];
#pragma unroll
                for (int mi = 0; mi < 2; mi++) {
                    mma_bf16(acc[mi][ni], ah[mi], bh);
                    mma_bf16(acc[mi][ni], ah[mi], bl);
                    mma_bf16(acc[mi][ni], al[mi], bh);
                }
            }
        }
        __syncthreads();
    }

#pragma unroll
    for (int mi = 0; mi < 2; mi++) {
#pragma unroll
        for (int ni = 0; ni < 8; ni++) {
            int col = n0 + wn * 64 + ni * 8 + 2 * c;
            float2 bb = *(const float2*)(bias + col);
            int row0 = m0 + wm * 32 + mi * 16 + g;
            float2 c0 = make_float2(acc[mi][ni][0] + bb.x, acc[mi][ni][1] + bb.y);
            float2 c1 = make_float2(acc[mi][ni][2] + bb.x, acc[mi][ni][3] + bb.y);
            *(float2*)(C + (size_t)row0 * N + col) = c0;
            *(float2*)(C + (size_t)(row0 + 8) * N + col) = c1;
        }
    }
}

__global__ __launch_bounds__(256, 2)
void gemm_qkv_kernel(const float* __restrict__ bqkv) {
    bf16pp_gemm_body(3 * DIM, g_xh, g_xl, g_Wqh, g_Wql, bqkv, g_qkv);
}

__global__ __launch_bounds__(256, 2)
void gemm_out_kernel(const float* __restrict__ bo) {
    bf16pp_gemm_body(DIM, g_Oh, g_Ol, g_Woh, g_Wol, bo, g_att);
}

// ---------------- causal flash attention, BF16x3 (R10 + split-O epilogue)
__global__ __launch_bounds__(256, 2)
void flash_bf16_kernel() {
    __shared__ __align__(16) __nv_bfloat16 Kh[KT][72], Kl[KT][72];
    __shared__ __align__(16) __nv_bfloat16 Vh[KT][72], Vl[KT][72];

    int h = blockIdx.y;
    int m0 = (gridDim.x - 1 - blockIdx.x) * 128;   // largest-work blocks first
    int tid = threadIdx.x;
    int w = tid >> 5, lane = tid & 31;
    int g = lane >> 2, c = lane & 3;
    int q0w = m0 + w * 16;

    unsigned qh[4][4], ql[4][4];
    {
        const float* Qb = g_Q + ((size_t)h * SEQ + q0w) * HD;
#pragma unroll
        for (int kk = 0; kk < 4; kk++) {
            float2 p0 = *(const float2*)(Qb + (size_t)g * HD + kk * 16 + 2 * c);
            float2 p1 = *(const float2*)(Qb + (size_t)(g + 8) * HD + kk * 16 + 2 * c);
            float2 p2 = *(const float2*)(Qb + (size_t)g * HD + kk * 16 + 2 * c + 8);
            float2 p3 = *(const float2*)(Qb + (size_t)(g + 8) * HD + kk * 16 + 2 * c + 8);
            split_pack(p0.x * 0.125f, p0.y * 0.125f, qh[kk][0], ql[kk][0]);
            split_pack(p1.x * 0.125f, p1.y * 0.125f, qh[kk][1], ql[kk][1]);
            split_pack(p2.x * 0.125f, p2.y * 0.125f, qh[kk][2], ql[kk][2]);
            split_pack(p3.x * 0.125f, p3.y * 0.125f, qh[kk][3], ql[kk][3]);
        }
    }

    int mrow = ((lane >> 4) & 1) * 8 + (lane & 7);
    int mcol = ((lane >> 3) & 1) * 8;
    unsigned kh_base = smem_u32(&Kh[mrow][mcol]);
    unsigned kl_base = smem_u32(&Kl[mrow][mcol]);
    unsigned vh_base = smem_u32(&Vh[lane & 15][(lane >> 4) * 8]);
    unsigned vl_base = smem_u32(&Vl[lane & 15][(lane >> 4) * 8]);

    float o[8][4];
#pragma unroll
    for (int nn = 0; nn < 8; nn++)
#pragma unroll
        for (int i = 0; i < 4; i++) o[nn][i] = 0.f;
    float mrw[2] = {-INFINITY, -INFINITY};
    float lrw[2] = {0.f, 0.f};

    int key = tid >> 3, dg = tid & 7;
    size_t lbase = ((size_t)h * SEQ + key) * (HD / 8) + dg;
    uint4 pkh = g_Kh4[lbase], pkl = g_Kl4[lbase];
    uint4 pvh = g_Vh4[lbase], pvl = g_Vl4[lbase];

    int nT = (m0 + 128) / KT;
    for (int t = 0; t < nT; t++) {
        int kt0 = t * KT;
        __syncthreads();

        *(uint4*)&Kh[key][dg * 8] = pkh;
        *(uint4*)&Kl[key][dg * 8] = pkl;
        *(uint4*)&Vh[key][dg * 8] = pvh;
        *(uint4*)&Vl[key][dg * 8] = pvl;
        __syncthreads();

        if (t + 1 < nT) {
            size_t roff = lbase + (size_t)(kt0 + KT) * (HD / 8);
            pkh = g_Kh4[roff]; pkl = g_Kl4[roff];
            pvh = g_Vh4[roff]; pvl = g_Vl4[roff];
        }

        if (kt0 <= q0w + 15) {
            float s[4][4];
#pragma unroll
            for (int nn = 0; nn < 4; nn++)
#pragma unroll
                for (int i = 0; i < 4; i++) s[nn][i] = 0.f;
#pragma unroll
            for (int kk = 0; kk < 4; kk++) {
#pragma unroll
                for (int q2 = 0; q2 < 2; q2++) {
                    unsigned bh4[4], bl4[4];
                    unsigned off = q2 * (16 * 144) + kk * 32;
                    ldsm_x4(bh4[0], bh4[1], bh4[2], bh4[3], kh_base + off);
                    ldsm_x4(bl4[0], bl4[1], bl4[2], bl4[3], kl_base + off);
                    mma_bf16(s[2 * q2],     qh[kk], bh4);
                    mma_bf16(s[2 * q2],     qh[kk], bl4);
                    mma_bf16(s[2 * q2],     ql[kk], bh4);
                    mma_bf16(s[2 * q2 + 1], qh[kk], bh4 + 2);
                    mma_bf16(s[2 * q2 + 1], qh[kk], bl4 + 2);
                    mma_bf16(s[2 * q2 + 1], ql[kk], bh4 + 2);
                }
            }

            float tmax[2] = {-INFINITY, -INFINITY};
#pragma unroll
            for (int nn = 0; nn < 4; nn++) {
#pragma unroll
                for (int i = 0; i < 4; i++) {
                    int qrow = q0w + g + ((i >> 1) << 3);
                    int kcol = kt0 + nn * 8 + 2 * c + (i & 1);
                    if (kcol > qrow) s[nn][i] = -INFINITY;
                    tmax[i >> 1] = fmaxf(tmax[i >> 1], s[nn][i]);
                }
            }
#pragma unroll
            for (int off = 1; off <= 2; off <<= 1) {
                tmax[0] = fmaxf(tmax[0], __shfl_xor_sync(0xffffffffu, tmax[0], off));
                tmax[1] = fmaxf(tmax[1], __shfl_xor_sync(0xffffffffu, tmax[1], off));
            }
            float mnew0 = fmaxf(mrw[0], tmax[0]);
            float mnew1 = fmaxf(mrw[1], tmax[1]);
            float corr0 = __expf(mrw[0] - mnew0);
            float corr1 = __expf(mrw[1] - mnew1);
            mrw[0] = mnew0; mrw[1] = mnew1;

            float rsum[2] = {0.f, 0.f};
#pragma unroll
            for (int nn = 0; nn < 4; nn++) {
#pragma unroll
                for (int i = 0; i < 4; i++) {
                    float p = __expf(s[nn][i] - ((i >> 1) ? mnew1 : mnew0));
                    s[nn][i] = p;
                    rsum[i >> 1] += p;
                }
            }
#pragma unroll
            for (int off = 1; off <= 2; off <<= 1) {
                rsum[0] += __shfl_xor_sync(0xffffffffu, rsum[0], off);
                rsum[1] += __shfl_xor_sync(0xffffffffu, rsum[1], off);
            }
            lrw[0] = lrw[0] * corr0 + rsum[0];
            lrw[1] = lrw[1] * corr1 + rsum[1];
#pragma unroll
            for (int nn = 0; nn < 8; nn++) {
                o[nn][0] *= corr0; o[nn][1] *= corr0;
                o[nn][2] *= corr1; o[nn][3] *= corr1;
            }

#pragma unroll
            for (int kk = 0; kk < 2; kk++) {
                unsigned ah[4], al[4];
                split_pack(s[2 * kk][0],     s[2 * kk][1],     ah[0], al[0]);
                split_pack(s[2 * kk][2],     s[2 * kk][3],     ah[1], al[1]);
                split_pack(s[2 * kk + 1][0], s[2 * kk + 1][1], ah[2], al[2]);
                split_pack(s[2 * kk + 1][2], s[2 * kk + 1][3], ah[3], al[3]);
#pragma unroll
                for (int np = 0; np < 4; np++) {
                    unsigned bh4[4], bl4[4];
                    unsigned off = kk * (16 * 144) + np * 32;
                    ldsm_x4_trans(bh4[0], bh4[1], bh4[2], bh4[3], vh_base + off);
                    ldsm_x4_trans(bl4[0], bl4[1], bl4[2], bl4[3], vl_base + off);
                    mma_bf16(o[np * 2],     ah, bh4);
                    mma_bf16(o[np * 2],     ah, bl4);
                    mma_bf16(o[np * 2],     al, bh4);
                    mma_bf16(o[np * 2 + 1], ah, bh4 + 2);
                    mma_bf16(o[np * 2 + 1], ah, bl4 + 2);
                    mma_bf16(o[np * 2 + 1], al, bh4 + 2);
                }
            }
        }
    }

    // ---- normalize + write O as pre-split bf16 kpair words ----
    float inv0 = 1.f / lrw[0];
    float inv1 = 1.f / lrw[1];
#pragma unroll
    for (int nn = 0; nn < 8; nn++) {
        int wi0 = (q0w + g) * (DIM / 2) + h * 32 + nn * 4 + c;
        int wi1 = (q0w + g + 8) * (DIM / 2) + h * 32 + nn * 4 + c;
        unsigned h0, l0, h1, l1;
        split_pack(o[nn][0] * inv0, o[nn][1] * inv0, h0, l0);
        split_pack(o[nn][2] * inv1, o[nn][3] * inv1, h1, l1);
        g_Oh[wi0] = h0; g_Ol[wi0] = l0;
        g_Oh[wi1] = h1; g_Ol[wi1] = l1;
    }
}

// ---------------- LayerNorm over last dim (1024) ------------------------
__global__ __launch_bounds__(256)
void layernorm_kernel(const float* __restrict__ gamma,
                      const float* __restrict__ beta,
                      float* __restrict__ Y) {
    int r = blockIdx.x;
    const float* x = g_att + (size_t)r * DIM;
    int tid = threadIdx.x;

    float s = 0.f, s2 = 0.f;
#pragma unroll
    for (int it = 0; it < DIM / 256; it++) {
        float v = x[tid + it * 256];
        s += v;
        s2 += v * v;
    }
#pragma unroll
    for (int off = 16; off; off >>= 1) {
        s  += __shfl_xor_sync(0xffffffffu, s, off);
        s2 += __shfl_xor_sync(0xffffffffu, s2, off);
    }
    __shared__ float ws[8], ws2[8];
    int w = tid >> 5, lane = tid & 31;
    if (lane == 0) { ws[w] = s; ws2[w] = s2; }
    __syncthreads();
    float S1 = 0.f, S2 = 0.f;
#pragma unroll
    for (int i = 0; i < 8; i++) { S1 += ws[i]; S2 += ws2[i]; }

    float mu  = S1 * (1.f / DIM);
    float var = S2 * (1.f / DIM) - mu * mu;
    float inv = rsqrtf(var + 1e-5f);
#pragma unroll
    for (int it = 0; it < DIM / 256; it++) {
        int j = tid + it * 256;
        float v = x[j];
        Y[(size_t)r * DIM + j] = (v - mu) * inv * gamma[j] + beta[j];
    }
}

// ---------------- launch ------------------------------------------------
extern "C" void kernel_launch(void* const* d_in, const int* in_sizes, int n_in,
                              void* d_out, int out_size) {
    const float* x     = (const float*)d_in[0];
    const float* Wqkv  = (const float*)d_in[1];
    const float* bqkv  = (const float*)d_in[2];
    const float* Wo    = (const float*)d_in[3];
    const float* bo    = (const float*)d_in[4];
    const float* gamma = (const float*)d_in[5];
    const float* beta  = (const float*)d_in[6];
    float* out = (float*)d_out;

    unsigned *Wqh, *Wql, *Woh, *Wol;
    cudaGetSymbolAddress((void**)&Wqh, g_Wqh);
    cudaGetSymbolAddress((void**)&Wql, g_Wql);
    cudaGetSymbolAddress((void**)&Woh, g_Woh);
    cudaGetSymbolAddress((void**)&Wol, g_Wol);

    cudaFuncSetAttribute(gemm_qkv_kernel,
                         cudaFuncAttributeMaxDynamicSharedMemorySize, GEMM_SMEM_BYTES);
    cudaFuncSetAttribute(gemm_out_kernel,
                         cudaFuncAttributeMaxDynamicSharedMemorySize, GEMM_SMEM_BYTES);

    rope_invf_kernel<<<2, 256>>>();
    rope_tables_kernel<<<(SEQ * 512) / 256, 256>>>();
    split_x_kernel<<<(SEQ * 512) / 256, 256>>>(x);
    split_w_kernel<<<(512 * 3 * DIM) / 256, 256>>>(Wqkv, Wqh, Wql, 3 * DIM);
    split_w_kernel<<<(512 * DIM) / 256, 256>>>(Wo, Woh, Wol, DIM);
    gemm_qkv_kernel<<<dim3(3 * DIM / 128, SEQ / 128), 256, GEMM_SMEM_BYTES>>>(bqkv);
    rope_scatter_kernel<<<(SEQ * DIM) / 256, 256>>>();
    flash_bf16_kernel<<<dim3(SEQ / 128, NH), 256>>>();
    gemm_out_kernel<<<dim3(DIM / 128, SEQ / 128), 256, GEMM_SMEM_BYTES>>>(bo);
    layernorm_kernel<<<SEQ, 256>>>(gamma, beta, out);
}

// round 15
// speedup vs baseline: 1.4500x; 1.4500x over previous
#include <cuda_runtime.h>
#include <cuda_bf16.h>
#include <math.h>

#define SEQ 4096
#define DIM 1024
#define NH  16
#define HD  64
#define KT  32   // keys per flash tile

// ---------------- device scratch (no allocation allowed) ----------------
__device__ float g_qkv[SEQ * 3 * DIM];      // QKV projection output (fp32)
__device__ float g_Q[NH * SEQ * HD];        // roped Q, head-major, fp32
__device__ uint4 g_Kh4[NH * SEQ * HD / 8];  // K bf16 hi, head-major
__device__ uint4 g_Kl4[NH * SEQ * HD / 8];  // K bf16 lo
__device__ uint4 g_Vh4[NH * SEQ * HD / 8];  // V bf16 hi
__device__ uint4 g_Vl4[NH * SEQ * HD / 8];  // V bf16 lo
__device__ unsigned g_xh[SEQ * DIM / 2];    // x split, row-major kpair words
__device__ unsigned g_xl[SEQ * DIM / 2];
__device__ unsigned g_Wqh[(DIM / 2) * (3 * DIM)];  // Wqkv split, kpair-packed
__device__ unsigned g_Wql[(DIM / 2) * (3 * DIM)];
__device__ unsigned g_Woh[(DIM / 2) * DIM];        // Wo split, kpair-packed
__device__ unsigned g_Wol[(DIM / 2) * DIM];
__device__ unsigned g_Oh[SEQ * DIM / 2];    // attention out split, row-major
__device__ unsigned g_Ol[SEQ * DIM / 2];
__device__ float g_att[SEQ * DIM];          // after out-proj, pre-LN
__device__ float g_cos[SEQ * 512];
__device__ float g_sin[SEQ * 512];
__device__ float g_invf[512];

// ---------------- BF16 helpers ------------------------------------------
__device__ __forceinline__ void mma_bf16(float* c, const unsigned* a, const unsigned* b) {
    asm volatile(
        "mma.sync.aligned.m16n8k16.row.col.f32.bf16.bf16.f32 "
        "{%0,%1,%2,%3}, {%4,%5,%6,%7}, {%8,%9}, {%0,%1,%2,%3};"
        : "+f"(c[0]), "+f"(c[1]), "+f"(c[2]), "+f"(c[3])
        : "r"(a[0]), "r"(a[1]), "r"(a[2]), "r"(a[3]), "r"(b[0]), "r"(b[1]));
}
__device__ __forceinline__ void split_pack(float a, float b, unsigned& h, unsigned& l) {
    __nv_bfloat16 ah = __float2bfloat16_rn(a);
    __nv_bfloat16 bh = __float2bfloat16_rn(b);
    float ar = a - __bfloat162float(ah);
    float br = b - __bfloat162float(bh);
    __nv_bfloat162 hv; hv.x = ah; hv.y = bh;
    __nv_bfloat162 lv = __floats2bfloat162_rn(ar, br);
    h = *reinterpret_cast<unsigned*>(&hv);
    l = *reinterpret_cast<unsigned*>(&lv);
}
__device__ __forceinline__ void ldsm_x4_trans(unsigned& r0, unsigned& r1,
                                              unsigned& r2, unsigned& r3, unsigned addr) {
    asm volatile("ldmatrix.sync.aligned.m8n8.x4.trans.shared.b16 {%0,%1,%2,%3}, [%4];"
                 : "=r"(r0), "=r"(r1), "=r"(r2), "=r"(r3) : "r"(addr));
}
__device__ __forceinline__ void ldsm_x4(unsigned& r0, unsigned& r1,
                                        unsigned& r2, unsigned& r3, unsigned addr) {
    asm volatile("ldmatrix.sync.aligned.m8n8.x4.shared.b16 {%0,%1,%2,%3}, [%4];"
                 : "=r"(r0), "=r"(r1), "=r"(r2), "=r"(r3) : "r"(addr));
}
__device__ __forceinline__ unsigned smem_u32(const void* p) {
    unsigned a;
    asm("{ .reg .u64 t; cvta.to.shared.u64 t, %1; cvt.u32.u64 %0, t; }" : "=r"(a) : "l"(p));
    return a;
}

// ---------------- operand pre-split kernels ------------------------------
__global__ void split_x_kernel(const float* __restrict__ x) {
    int idx = blockIdx.x * blockDim.x + threadIdx.x;   // SEQ*512
    float2 v = ((const float2*)x)[idx];
    split_pack(v.x, v.y, g_xh[idx], g_xl[idx]);
}
// W: [1024][N] fp32 -> kpair-packed [512][N]: word(kp,n) = {W[2kp][n], W[2kp+1][n]}
__global__ void split_w_kernel(const float* __restrict__ W, unsigned* __restrict__ wh,
                               unsigned* __restrict__ wl, int N) {
    int idx = blockIdx.x * blockDim.x + threadIdx.x;   // 512*N
    int kp = idx / N, n = idx - kp * N;
    float a = W[(size_t)(2 * kp) * N + n];
    float b = W[(size_t)(2 * kp + 1) * N + n];
    split_pack(a, b, wh[idx], wl[idx]);
}

// ---------------- RoPE tables -------------------------------------------
__global__ void rope_invf_kernel() {
    int i = blockIdx.x * blockDim.x + threadIdx.x;
    if (i < 512)
        g_invf[i] = (float)exp(-((double)i) * (9.210340371976184 / 512.0));
}
__global__ void rope_tables_kernel() {
    int idx = blockIdx.x * blockDim.x + threadIdx.x;
    if (idx >= SEQ * 512) return;
    int s = idx >> 9;
    int i = idx & 511;
    float ang = (float)s * g_invf[i];
    double a = (double)ang;
    double k = rint(a * 0.15915494309189535);
    float r = (float)(a - k * 6.283185307179586);
    g_cos[idx] = cosf(r);
    g_sin[idx] = sinf(r);
}

// ---------------- RoPE apply + head-major scatter + bf16 hi/lo split ----
__global__ void rope_scatter_kernel() {
    int idx = blockIdx.x * blockDim.x + threadIdx.x;   // SEQ*DIM threads
    int s = idx >> 10;
    int j = idx & 1023;
    int i = j & 511;
    float c  = g_cos[(s << 9) + i];
    float sn = g_sin[(s << 9) + i];
    const float* row = g_qkv + (size_t)s * (3 * DIM);
    float q = row[j];
    float k = row[DIM + j];
    float v = row[2 * DIM + j];
    float q2, k2;
    if (j < 512) { q2 = -row[j + 512];       k2 = -row[DIM + j + 512]; }
    else         { q2 =  row[j - 512];       k2 =  row[DIM + j - 512]; }
    float qo = q * c + q2 * sn;
    float ko = k * c + k2 * sn;
    int h = j >> 6, d = j & 63;
    int o = ((h * SEQ) + s) * HD + d;
    g_Q[o] = qo;
    __nv_bfloat16 kh = __float2bfloat16_rn(ko);
    ((__nv_bfloat16*)g_Kh4)[o] = kh;
    ((__nv_bfloat16*)g_Kl4)[o] = __float2bfloat16_rn(ko - __bfloat162float(kh));
    __nv_bfloat16 vh = __float2bfloat16_rn(v);
    ((__nv_bfloat16*)g_Vh4)[o] = vh;
    ((__nv_bfloat16*)g_Vl4)[o] = __float2bfloat16_rn(v - __bfloat162float(vh));
}

// ---------------- BF16x3 GEMM on pre-split operands (R10 structure) -----
// 128x128x32 tile, 256 threads = 8 warps (4m x 2n), warp tile 32x64.
// Fill is a pure uint4 copy of pre-split kpair words; compute loop = R10.
__device__ __forceinline__
void bf16_gemm_presplit_body(int N,
                             const unsigned* __restrict__ Ah,
                             const unsigned* __restrict__ Al,
                             const unsigned* __restrict__ Bh,
                             const unsigned* __restrict__ Bl,
                             const float* __restrict__ bias,
                             float* __restrict__ C) {
    __shared__ unsigned As_h[128][20], As_l[128][20];
    __shared__ unsigned Bs_h[16][136], Bs_l[16][136];

    const int KW = DIM / 2;   // 512 kpair words per A row
    int tid = threadIdx.x;
    int w = tid >> 5, lane = tid & 31;
    int g = lane >> 2, c = lane & 3;
    int m0 = blockIdx.y * 128, n0 = blockIdx.x * 128;
    int wm = w >> 1, wn = w & 1;

    float acc[2][8][4];
#pragma unroll
    for (int mi = 0; mi < 2; mi++)
#pragma unroll
        for (int ni = 0; ni < 8; ni++)
#pragma unroll
            for (int i = 0; i < 4; i++) acc[mi][ni][i] = 0.f;

    int am = tid >> 1, akp = (tid & 1) * 8;   // A fill: row, kpair offset
    int bkp = tid >> 4, bn8 = (tid & 15) * 8; // B fill: kpair row, n offset
    const unsigned* Agh = Ah + (size_t)(m0 + am) * KW + akp;
    const unsigned* Agl = Al + (size_t)(m0 + am) * KW + akp;
    const unsigned* Bgh = Bh + (size_t)bkp * N + n0 + bn8;
    const unsigned* Bgl = Bl + (size_t)bkp * N + n0 + bn8;

    for (int cc = 0; cc < 32; cc++) {
        // ---- pure-copy fill (16 kpairs of K per chunk) ----
        const unsigned* agh = Agh + cc * 16;
        const unsigned* agl = Agl + cc * 16;
        uint4 va0 = *(const uint4*)agh;
        uint4 va1 = *(const uint4*)(agh + 4);
        uint4 vb0 = *(const uint4*)agl;
        uint4 vb1 = *(const uint4*)(agl + 4);
        const unsigned* bgh = Bgh + (size_t)cc * 16 * N;
        const unsigned* bgl = Bgl + (size_t)cc * 16 * N;
        uint4 vc0 = *(const uint4*)bgh;
        uint4 vc1 = *(const uint4*)(bgh + 4);
        uint4 vd0 = *(const uint4*)bgl;
        uint4 vd1 = *(const uint4*)(bgl + 4);
        *(uint4*)&As_h[am][akp]     = va0;
        *(uint4*)&As_h[am][akp + 4] = va1;
        *(uint4*)&As_l[am][akp]     = vb0;
        *(uint4*)&As_l[am][akp + 4] = vb1;
        *(uint4*)&Bs_h[bkp][bn8]     = vc0;
        *(uint4*)&Bs_h[bkp][bn8 + 4] = vc1;
        *(uint4*)&Bs_l[bkp][bn8]     = vd0;
        *(uint4*)&Bs_l[bkp][bn8 + 4] = vd1;
        __syncthreads();

#pragma unroll
        for (int kk = 0; kk < 2; kk++) {
            unsigned ah[2][4], al[2][4];
#pragma unroll
            for (int mi = 0; mi < 2; mi++) {
                int rb = wm * 32 + mi * 16;
                ah[mi][0] = As_h[rb + g][kk * 8 + c];
                ah[mi][1] = As_h[rb + g + 8][kk * 8 + c];
                ah[mi][2] = As_h[rb + g][kk * 8 + c + 4];
                ah[mi][3] = As_h[rb + g + 8][kk * 8 + c + 4];
                al[mi][0] = As_l[rb + g][kk * 8 + c];
                al[mi][1] = As_l[rb + g + 8][kk * 8 + c];
                al[mi][2] = As_l[rb + g][kk * 8 + c + 4];
                al[mi][3] = As_l[rb + g + 8][kk * 8 + c + 4];
            }
#pragma unroll
            for (int ni = 0; ni < 8; ni++) {
                int nb = wn * 64 + ni * 8 + g;
                unsigned bh[2], bl[2];
                bh[0] = Bs_h[kk * 8 + c][nb];
                bh[1] = Bs_h[kk * 8 + c + 4][nb];
                bl[0] = Bs_l[kk * 8 + c][nb];
                bl[1] = Bs_l[kk * 8 + c + 4][nb];
#pragma unroll
                for (int mi = 0; mi < 2; mi++) {
                    mma_bf16(acc[mi][ni], ah[mi], bh);
                    mma_bf16(acc[mi][ni], ah[mi], bl);
                    mma_bf16(acc[mi][ni], al[mi], bh);
                }
            }
        }
        __syncthreads();
    }

#pragma unroll
    for (int mi = 0; mi < 2; mi++) {
#pragma unroll
        for (int ni = 0; ni < 8; ni++) {
            int col = n0 + wn * 64 + ni * 8 + 2 * c;
            float2 bb = *(const float2*)(bias + col);
            int row0 = m0 + wm * 32 + mi * 16 + g;
            float2 c0 = make_float2(acc[mi][ni][0] + bb.x, acc[mi][ni][1] + bb.y);
            float2 c1 = make_float2(acc[mi][ni][2] + bb.x, acc[mi][ni][3] + bb.y);
            *(float2*)(C + (size_t)row0 * N + col) = c0;
            *(float2*)(C + (size_t)(row0 + 8) * N + col) = c1;
        }
    }
}

__global__ __launch_bounds__(256, 2)
void gemm_qkv_kernel(const float* __restrict__ bqkv) {
    bf16_gemm_presplit_body(3 * DIM, g_xh, g_xl, g_Wqh, g_Wql, bqkv, g_qkv);
}

__global__ __launch_bounds__(256, 2)
void gemm_out_kernel(const float* __restrict__ bo) {
    bf16_gemm_presplit_body(DIM, g_Oh, g_Ol, g_Woh, g_Wol, bo, g_att);
}

// ---------------- causal flash attention, BF16x3 (R10 + split-O epilogue)
__global__ __launch_bounds__(256, 2)
void flash_bf16_kernel() {
    __shared__ __align__(16) __nv_bfloat16 Kh[KT][72], Kl[KT][72];
    __shared__ __align__(16) __nv_bfloat16 Vh[KT][72], Vl[KT][72];

    int h = blockIdx.y;
    int m0 = blockIdx.x * 128;
    int tid = threadIdx.x;
    int w = tid >> 5, lane = tid & 31;
    int g = lane >> 2, c = lane & 3;
    int q0w = m0 + w * 16;

    unsigned qh[4][4], ql[4][4];
    {
        const float* Qb = g_Q + ((size_t)h * SEQ + q0w) * HD;
#pragma unroll
        for (int kk = 0; kk < 4; kk++) {
            float2 p0 = *(const float2*)(Qb + (size_t)g * HD + kk * 16 + 2 * c);
            float2 p1 = *(const float2*)(Qb + (size_t)(g + 8) * HD + kk * 16 + 2 * c);
            float2 p2 = *(const float2*)(Qb + (size_t)g * HD + kk * 16 + 2 * c + 8);
            float2 p3 = *(const float2*)(Qb + (size_t)(g + 8) * HD + kk * 16 + 2 * c + 8);
            split_pack(p0.x * 0.125f, p0.y * 0.125f, qh[kk][0], ql[kk][0]);
            split_pack(p1.x * 0.125f, p1.y * 0.125f, qh[kk][1], ql[kk][1]);
            split_pack(p2.x * 0.125f, p2.y * 0.125f, qh[kk][2], ql[kk][2]);
            split_pack(p3.x * 0.125f, p3.y * 0.125f, qh[kk][3], ql[kk][3]);
        }
    }

    int mrow = ((lane >> 4) & 1) * 8 + (lane & 7);
    int mcol = ((lane >> 3) & 1) * 8;
    unsigned kh_base = smem_u32(&Kh[mrow][mcol]);
    unsigned kl_base = smem_u32(&Kl[mrow][mcol]);
    unsigned vh_base = smem_u32(&Vh[lane & 15][(lane >> 4) * 8]);
    unsigned vl_base = smem_u32(&Vl[lane & 15][(lane >> 4) * 8]);

    float o[8][4];
#pragma unroll
    for (int nn = 0; nn < 8; nn++)
#pragma unroll
        for (int i = 0; i < 4; i++) o[nn][i] = 0.f;
    float mrw[2] = {-INFINITY, -INFINITY};
    float lrw[2] = {0.f, 0.f};

    int key = tid >> 3, dg = tid & 7;
    size_t lbase = ((size_t)h * SEQ + key) * (HD / 8) + dg;
    uint4 pkh = g_Kh4[lbase], pkl = g_Kl4[lbase];
    uint4 pvh = g_Vh4[lbase], pvl = g_Vl4[lbase];

    int nT = (m0 + 128) / KT;
    for (int t = 0; t < nT; t++) {
        int kt0 = t * KT;
        __syncthreads();

        *(uint4*)&Kh[key][dg * 8] = pkh;
        *(uint4*)&Kl[key][dg * 8] = pkl;
        *(uint4*)&Vh[key][dg * 8] = pvh;
        *(uint4*)&Vl[key][dg * 8] = pvl;
        __syncthreads();

        if (t + 1 < nT) {
            size_t roff = lbase + (size_t)(kt0 + KT) * (HD / 8);
            pkh = g_Kh4[roff]; pkl = g_Kl4[roff];
            pvh = g_Vh4[roff]; pvl = g_Vl4[roff];
        }

        if (kt0 <= q0w + 15) {
            float s[4][4];
#pragma unroll
            for (int nn = 0; nn < 4; nn++)
#pragma unroll
                for (int i = 0; i < 4; i++) s[nn][i] = 0.f;
#pragma unroll
            for (int kk = 0; kk < 4; kk++) {
#pragma unroll
                for (int q2 = 0; q2 < 2; q2++) {
                    unsigned bh4[4], bl4[4];
                    unsigned off = q2 * (16 * 144) + kk * 32;
                    ldsm_x4(bh4[0], bh4[1], bh4[2], bh4[3], kh_base + off);
                    ldsm_x4(bl4[0], bl4[1], bl4[2], bl4[3], kl_base + off);
                    mma_bf16(s[2 * q2],     qh[kk], bh4);
                    mma_bf16(s[2 * q2],     qh[kk], bl4);
                    mma_bf16(s[2 * q2],     ql[kk], bh4);
                    mma_bf16(s[2 * q2 + 1], qh[kk], bh4 + 2);
                    mma_bf16(s[2 * q2 + 1], qh[kk], bl4 + 2);
                    mma_bf16(s[2 * q2 + 1], ql[kk], bh4 + 2);
                }
            }

            float tmax[2] = {-INFINITY, -INFINITY};
#pragma unroll
            for (int nn = 0; nn < 4; nn++) {
#pragma unroll
                for (int i = 0; i < 4; i++) {
                    int qrow = q0w + g + ((i >> 1) << 3);
                    int kcol = kt0 + nn * 8 + 2 * c + (i & 1);
                    if (kcol > qrow) s[nn][i] = -INFINITY;
                    tmax[i >> 1] = fmaxf(tmax[i >> 1], s[nn][i]);
                }
            }
#pragma unroll
            for (int off = 1; off <= 2; off <<= 1) {
                tmax[0] = fmaxf(tmax[0], __shfl_xor_sync(0xffffffffu, tmax[0], off));
                tmax[1] = fmaxf(tmax[1], __shfl_xor_sync(0xffffffffu, tmax[1], off));
            }
            float mnew0 = fmaxf(mrw[0], tmax[0]);
            float mnew1 = fmaxf(mrw[1], tmax[1]);
            float corr0 = __expf(mrw[0] - mnew0);
            float corr1 = __expf(mrw[1] - mnew1);
            mrw[0] = mnew0; mrw[1] = mnew1;

            float rsum[2] = {0.f, 0.f};
#pragma unroll
            for (int nn = 0; nn < 4; nn++) {
#pragma unroll
                for (int i = 0; i < 4; i++) {
                    float p = __expf(s[nn][i] - ((i >> 1) ? mnew1 : mnew0));
                    s[nn][i] = p;
                    rsum[i >> 1] += p;
                }
            }
#pragma unroll
            for (int off = 1; off <= 2; off <<= 1) {
                rsum[0] += __shfl_xor_sync(0xffffffffu, rsum[0], off);
                rsum[1] += __shfl_xor_sync(0xffffffffu, rsum[1], off);
            }
            lrw[0] = lrw[0] * corr0 + rsum[0];
            lrw[1] = lrw[1] * corr1 + rsum[1];
#pragma unroll
            for (int nn = 0; nn < 8; nn++) {
                o[nn][0] *= corr0; o[nn][1] *= corr0;
                o[nn][2] *= corr1; o[nn][3] *= corr1;
            }

#pragma unroll
            for (int kk = 0; kk < 2; kk++) {
                unsigned ah[4], al[4];
                split_pack(s[2 * kk][0],     s[2 * kk][1],     ah[0], al[0]);
                split_pack(s[2 * kk][2],     s[2 * kk][3],     ah[1], al[1]);
                split_pack(s[2 * kk + 1][0], s[2 * kk + 1][1], ah[2], al[2]);
                split_pack(s[2 * kk + 1][2], s[2 * kk + 1][3], ah[3], al[3]);
#pragma unroll
                for (int np = 0; np < 4; np++) {
                    unsigned bh4[4], bl4[4];
                    unsigned off = kk * (16 * 144) + np * 32;
                    ldsm_x4_trans(bh4[0], bh4[1], bh4[2], bh4[3], vh_base + off);
                    ldsm_x4_trans(bl4[0], bl4[1], bl4[2], bl4[3], vl_base + off);
                    mma_bf16(o[np * 2],     ah, bh4);
                    mma_bf16(o[np * 2],     ah, bl4);
                    mma_bf16(o[np * 2],     al, bh4);
                    mma_bf16(o[np * 2 + 1], ah, bh4 + 2);
                    mma_bf16(o[np * 2 + 1], ah, bl4 + 2);
                    mma_bf16(o[np * 2 + 1], al, bh4 + 2);
                }
            }
        }
    }

    // ---- normalize + write O as pre-split bf16 kpair words ----
    float inv0 = 1.f / lrw[0];
    float inv1 = 1.f / lrw[1];
#pragma unroll
    for (int nn = 0; nn < 8; nn++) {
        int wi0 = (q0w + g) * (DIM / 2) + h * 32 + nn * 4 + c;
        int wi1 = (q0w + g + 8) * (DIM / 2) + h * 32 + nn * 4 + c;
        unsigned h0, l0, h1, l1;
        split_pack(o[nn][0] * inv0, o[nn][1] * inv0, h0, l0);
        split_pack(o[nn][2] * inv1, o[nn][3] * inv1, h1, l1);
        g_Oh[wi0] = h0; g_Ol[wi0] = l0;
        g_Oh[wi1] = h1; g_Ol[wi1] = l1;
    }
}

// ---------------- LayerNorm over last dim (1024) ------------------------
__global__ __launch_bounds__(256)
void layernorm_kernel(const float* __restrict__ gamma,
                      const float* __restrict__ beta,
                      float* __restrict__ Y) {
    int r = blockIdx.x;
    const float* x = g_att + (size_t)r * DIM;
    int tid = threadIdx.x;

    float s = 0.f, s2 = 0.f;
#pragma unroll
    for (int it = 0; it < DIM / 256; it++) {
        float v = x[tid + it * 256];
        s += v;
        s2 += v * v;
    }
#pragma unroll
    for (int off = 16; off; off >>= 1) {
        s  += __shfl_xor_sync(0xffffffffu, s, off);
        s2 += __shfl_xor_sync(0xffffffffu, s2, off);
    }
    __shared__ float ws[8], ws2[8];
    int w = tid >> 5, lane = tid & 31;
    if (lane == 0) { ws[w] = s; ws2[w] = s2; }
    __syncthreads();
    float S1 = 0.f, S2 = 0.f;
#pragma unroll
    for (int i = 0; i < 8; i++) { S1 += ws[i]; S2 += ws2[i]; }

    float mu  = S1 * (1.f / DIM);
    float var = S2 * (1.f / DIM) - mu * mu;
    float inv = rsqrtf(var + 1e-5f);
#pragma unroll
    for (int it = 0; it < DIM / 256; it++) {
        int j = tid + it * 256;
        float v = x[j];
        Y[(size_t)r * DIM + j] = (v - mu) * inv * gamma[j] + beta[j];
    }
}

// ---------------- launch ------------------------------------------------
extern "C" void kernel_launch(void* const* d_in, const int* in_sizes, int n_in,
                              void* d_out, int out_size) {
    const float* x     = (const float*)d_in[0];
    const float* Wqkv  = (const float*)d_in[1];
    const float* bqkv  = (const float*)d_in[2];
    const float* Wo    = (const float*)d_in[3];
    const float* bo    = (const float*)d_in[4];
    const float* gamma = (const float*)d_in[5];
    const float* beta  = (const float*)d_in[6];
    float* out = (float*)d_out;

    unsigned *Wqh, *Wql, *Woh, *Wol;
    cudaGetSymbolAddress((void**)&Wqh, g_Wqh);
    cudaGetSymbolAddress((void**)&Wql, g_Wql);
    cudaGetSymbolAddress((void**)&Woh, g_Woh);
    cudaGetSymbolAddress((void**)&Wol, g_Wol);

    rope_invf_kernel<<<2, 256>>>();
    rope_tables_kernel<<<(SEQ * 512) / 256, 256>>>();
    split_x_kernel<<<(SEQ * 512) / 256, 256>>>(x);
    split_w_kernel<<<(512 * 3 * DIM) / 256, 256>>>(Wqkv, Wqh, Wql, 3 * DIM);
    split_w_kernel<<<(512 * DIM) / 256, 256>>>(Wo, Woh, Wol, DIM);
    gemm_qkv_kernel<<<dim3(3 * DIM / 128, SEQ / 128), 256>>>(bqkv);
    rope_scatter_kernel<<<(SEQ * DIM) / 256, 256>>>();
    flash_bf16_kernel<<<dim3(SEQ / 128, NH), 256>>>();
    gemm_out_kernel<<<dim3(DIM / 128, SEQ / 128), 256>>>(bo);
    layernorm_kernel<<<SEQ, 256>>>(gamma, beta, out);
}

// round 16
// speedup vs baseline: 1.4637x; 1.0095x over previous
#include <cuda_runtime.h>
#include <cuda_bf16.h>
#include <math.h>

#define SEQ 4096
#define DIM 1024
#define NH  16
#define HD  64
#define KT  32   // keys per flash tile

// ---------------- device scratch (no allocation allowed) ----------------
__device__ float g_qkv[SEQ * 3 * DIM];      // QKV projection output (fp32)
__device__ float g_Q[NH * SEQ * HD];        // roped Q, head-major, fp32
__device__ uint4 g_Kh4[NH * SEQ * HD / 8];  // K bf16 hi, head-major
__device__ uint4 g_Kl4[NH * SEQ * HD / 8];  // K bf16 lo
__device__ uint4 g_Vh4[NH * SEQ * HD / 8];  // V bf16 hi
__device__ uint4 g_Vl4[NH * SEQ * HD / 8];  // V bf16 lo
__device__ unsigned g_xh[SEQ * DIM / 2];    // x split, row-major kpair words
__device__ unsigned g_xl[SEQ * DIM / 2];
__device__ unsigned g_Wqh[(DIM / 2) * (3 * DIM)];  // Wqkv split, kpair-packed
__device__ unsigned g_Wql[(DIM / 2) * (3 * DIM)];
__device__ unsigned g_Woh[(DIM / 2) * DIM];        // Wo split, kpair-packed
__device__ unsigned g_Wol[(DIM / 2) * DIM];
__device__ unsigned g_Oh[SEQ * DIM / 2];    // attention out split, row-major
__device__ unsigned g_Ol[SEQ * DIM / 2];
__device__ float g_att[SEQ * DIM];          // after out-proj, pre-LN
__device__ float g_cos[SEQ * 512];
__device__ float g_sin[SEQ * 512];
__device__ float g_invf[512];

// ---------------- BF16 helpers ------------------------------------------
__device__ __forceinline__ void mma_bf16(float* c, const unsigned* a, const unsigned* b) {
    asm volatile(
        "mma.sync.aligned.m16n8k16.row.col.f32.bf16.bf16.f32 "
        "{%0,%1,%2,%3}, {%4,%5,%6,%7}, {%8,%9}, {%0,%1,%2,%3};"
        : "+f"(c[0]), "+f"(c[1]), "+f"(c[2]), "+f"(c[3])
        : "r"(a[0]), "r"(a[1]), "r"(a[2]), "r"(a[3]), "r"(b[0]), "r"(b[1]));
}
__device__ __forceinline__ void split_pack(float a, float b, unsigned& h, unsigned& l) {
    __nv_bfloat16 ah = __float2bfloat16_rn(a);
    __nv_bfloat16 bh = __float2bfloat16_rn(b);
    float ar = a - __bfloat162float(ah);
    float br = b - __bfloat162float(bh);
    __nv_bfloat162 hv; hv.x = ah; hv.y = bh;
    __nv_bfloat162 lv = __floats2bfloat162_rn(ar, br);
    h = *reinterpret_cast<unsigned*>(&hv);
    l = *reinterpret_cast<unsigned*>(&lv);
}
__device__ __forceinline__ void ldsm_x4_trans(unsigned& r0, unsigned& r1,
                                              unsigned& r2, unsigned& r3, unsigned addr) {
    asm volatile("ldmatrix.sync.aligned.m8n8.x4.trans.shared.b16 {%0,%1,%2,%3}, [%4];"
                 : "=r"(r0), "=r"(r1), "=r"(r2), "=r"(r3) : "r"(addr));
}
__device__ __forceinline__ void ldsm_x4(unsigned& r0, unsigned& r1,
                                        unsigned& r2, unsigned& r3, unsigned addr) {
    asm volatile("ldmatrix.sync.aligned.m8n8.x4.shared.b16 {%0,%1,%2,%3}, [%4];"
                 : "=r"(r0), "=r"(r1), "=r"(r2), "=r"(r3) : "r"(addr));
}
__device__ __forceinline__ unsigned smem_u32(const void* p) {
    unsigned a;
    asm("{ .reg .u64 t; cvta.to.shared.u64 t, %1; cvt.u32.u64 %0, t; }" : "=r"(a) : "l"(p));
    return a;
}

// ---------------- operand pre-split kernels ------------------------------
__global__ void split_x_kernel(const float* __restrict__ x) {
    int idx = blockIdx.x * blockDim.x + threadIdx.x;   // SEQ*512
    float2 v = ((const float2*)x)[idx];
    split_pack(v.x, v.y, g_xh[idx], g_xl[idx]);
}
// W: [1024][N] fp32 -> kpair-packed [512][N]: word(kp,n) = {W[2kp][n], W[2kp+1][n]}
__global__ void split_w_kernel(const float* __restrict__ W, unsigned* __restrict__ wh,
                               unsigned* __restrict__ wl, int N) {
    int idx = blockIdx.x * blockDim.x + threadIdx.x;   // 512*N
    int kp = idx / N, n = idx - kp * N;
    float a = W[(size_t)(2 * kp) * N + n];
    float b = W[(size_t)(2 * kp + 1) * N + n];
    split_pack(a, b, wh[idx], wl[idx]);
}

// ---------------- RoPE tables -------------------------------------------
__global__ void rope_invf_kernel() {
    int i = blockIdx.x * blockDim.x + threadIdx.x;
    if (i < 512)
        g_invf[i] = (float)exp(-((double)i) * (9.210340371976184 / 512.0));
}
__global__ void rope_tables_kernel() {
    int idx = blockIdx.x * blockDim.x + threadIdx.x;
    if (idx >= SEQ * 512) return;
    int s = idx >> 9;
    int i = idx & 511;
    float ang = (float)s * g_invf[i];
    double a = (double)ang;
    double k = rint(a * 0.15915494309189535);
    float r = (float)(a - k * 6.283185307179586);
    g_cos[idx] = cosf(r);
    g_sin[idx] = sinf(r);
}

// ---------------- RoPE apply + head-major scatter + bf16 hi/lo split ----
__global__ void rope_scatter_kernel() {
    int idx = blockIdx.x * blockDim.x + threadIdx.x;   // SEQ*DIM threads
    int s = idx >> 10;
    int j = idx & 1023;
    int i = j & 511;
    float c  = g_cos[(s << 9) + i];
    float sn = g_sin[(s << 9) + i];
    const float* row = g_qkv + (size_t)s * (3 * DIM);
    float q = row[j];
    float k = row[DIM + j];
    float v = row[2 * DIM + j];
    float q2, k2;
    if (j < 512) { q2 = -row[j + 512];       k2 = -row[DIM + j + 512]; }
    else         { q2 =  row[j - 512];       k2 =  row[DIM + j - 512]; }
    float qo = q * c + q2 * sn;
    float ko = k * c + k2 * sn;
    int h = j >> 6, d = j & 63;
    int o = ((h * SEQ) + s) * HD + d;
    g_Q[o] = qo;
    __nv_bfloat16 kh = __float2bfloat16_rn(ko);
    ((__nv_bfloat16*)g_Kh4)[o] = kh;
    ((__nv_bfloat16*)g_Kl4)[o] = __float2bfloat16_rn(ko - __bfloat162float(kh));
    __nv_bfloat16 vh = __float2bfloat16_rn(v);
    ((__nv_bfloat16*)g_Vh4)[o] = vh;
    ((__nv_bfloat16*)g_Vl4)[o] = __float2bfloat16_rn(v - __bfloat162float(vh));
}

// ---------------- BF16x3 GEMM on pre-split operands (R10 structure) -----
__device__ __forceinline__
void bf16_gemm_presplit_body(int N,
                             const unsigned* __restrict__ Ah,
                             const unsigned* __restrict__ Al,
                             const unsigned* __restrict__ Bh,
                             const unsigned* __restrict__ Bl,
                             const float* __restrict__ bias,
                             float* __restrict__ C) {
    __shared__ unsigned As_h[128][20], As_l[128][20];
    __shared__ unsigned Bs_h[16][136], Bs_l[16][136];

    const int KW = DIM / 2;   // 512 kpair words per A row
    int tid = threadIdx.x;
    int w = tid >> 5, lane = tid & 31;
    int g = lane >> 2, c = lane & 3;
    int m0 = blockIdx.y * 128, n0 = blockIdx.x * 128;
    int wm = w >> 1, wn = w & 1;

    float acc[2][8][4];
#pragma unroll
    for (int mi = 0; mi < 2; mi++)
#pragma unroll
        for (int ni = 0; ni < 8; ni++)
#pragma unroll
            for (int i = 0; i < 4; i++) acc[mi][ni][i] = 0.f;

    int am = tid >> 1, akp = (tid & 1) * 8;   // A fill: row, kpair offset
    int bkp = tid >> 4, bn8 = (tid & 15) * 8; // B fill: kpair row, n offset
    const unsigned* Agh = Ah + (size_t)(m0 + am) * KW + akp;
    const unsigned* Agl = Al + (size_t)(m0 + am) * KW + akp;
    const unsigned* Bgh = Bh + (size_t)bkp * N + n0 + bn8;
    const unsigned* Bgl = Bl + (size_t)bkp * N + n0 + bn8;

    for (int cc = 0; cc < 32; cc++) {
        const unsigned* agh = Agh + cc * 16;
        const unsigned* agl = Agl + cc * 16;
        uint4 va0 = *(const uint4*)agh;
        uint4 va1 = *(const uint4*)(agh + 4);
        uint4 vb0 = *(const uint4*)agl;
        uint4 vb1 = *(const uint4*)(agl + 4);
        const unsigned* bgh = Bgh + (size_t)cc * 16 * N;
        const unsigned* bgl = Bgl + (size_t)cc * 16 * N;
        uint4 vc0 = *(const uint4*)bgh;
        uint4 vc1 = *(const uint4*)(bgh + 4);
        uint4 vd0 = *(const uint4*)bgl;
        uint4 vd1 = *(const uint4*)(bgl + 4);
        *(uint4*)&As_h[am][akp]     = va0;
        *(uint4*)&As_h[am][akp + 4] = va1;
        *(uint4*)&As_l[am][akp]     = vb0;
        *(uint4*)&As_l[am][akp + 4] = vb1;
        *(uint4*)&Bs_h[bkp][bn8]     = vc0;
        *(uint4*)&Bs_h[bkp][bn8 + 4] = vc1;
        *(uint4*)&Bs_l[bkp][bn8]     = vd0;
        *(uint4*)&Bs_l[bkp][bn8 + 4] = vd1;
        __syncthreads();

#pragma unroll
        for (int kk = 0; kk < 2; kk++) {
            unsigned ah[2][4], al[2][4];
#pragma unroll
            for (int mi = 0; mi < 2; mi++) {
                int rb = wm * 32 + mi * 16;
                ah[mi][0] = As_h[rb + g][kk * 8 + c];
                ah[mi][1] = As_h[rb + g + 8][kk * 8 + c];
                ah[mi][2] = As_h[rb + g][kk * 8 + c + 4];
                ah[mi][3] = As_h[rb + g + 8][kk * 8 + c + 4];
                al[mi][0] = As_l[rb + g][kk * 8 + c];
                al[mi][1] = As_l[rb + g + 8][kk * 8 + c];
                al[mi][2] = As_l[rb + g][kk * 8 + c + 4];
                al[mi][3] = As_l[rb + g + 8][kk * 8 + c + 4];
            }
#pragma unroll
            for (int ni = 0; ni < 8; ni++) {
                int nb = wn * 64 + ni * 8 + g;
                unsigned bh[2], bl[2];
                bh[0] = Bs_h[kk * 8 + c][nb];
                bh[1] = Bs_h[kk * 8 + c + 4][nb];
                bl[0] = Bs_l[kk * 8 + c][nb];
                bl[1] = Bs_l[kk * 8 + c + 4][nb];
#pragma unroll
                for (int mi = 0; mi < 2; mi++) {
                    mma_bf16(acc[mi][ni], ah[mi], bh);
                    mma_bf16(acc[mi][ni], ah[mi], bl);
                    mma_bf16(acc[mi][ni], al[mi], bh);
                }
            }
        }
        __syncthreads();
    }

#pragma unroll
    for (int mi = 0; mi < 2; mi++) {
#pragma unroll
        for (int ni = 0; ni < 8; ni++) {
            int col = n0 + wn * 64 + ni * 8 + 2 * c;
            float2 bb = *(const float2*)(bias + col);
            int row0 = m0 + wm * 32 + mi * 16 + g;
            float2 c0 = make_float2(acc[mi][ni][0] + bb.x, acc[mi][ni][1] + bb.y);
            float2 c1 = make_float2(acc[mi][ni][2] + bb.x, acc[mi][ni][3] + bb.y);
            *(float2*)(C + (size_t)row0 * N + col) = c0;
            *(float2*)(C + (size_t)(row0 + 8) * N + col) = c1;
        }
    }
}

__global__ __launch_bounds__(256, 2)
void gemm_qkv_kernel(const float* __restrict__ bqkv) {
    bf16_gemm_presplit_body(3 * DIM, g_xh, g_xl, g_Wqh, g_Wql, bqkv, g_qkv);
}

__global__ __launch_bounds__(256, 2)
void gemm_out_kernel(const float* __restrict__ bo) {
    bf16_gemm_presplit_body(DIM, g_Oh, g_Ol, g_Woh, g_Wol, bo, g_att);
}

// ---------------- causal flash attention, BF16x3 -------------------------
// Heaviest query blocks launch first (reversed mapping) to kill the
// 2-wave causal-triangle tail.
__global__ __launch_bounds__(256, 2)
void flash_bf16_kernel() {
    __shared__ __align__(16) __nv_bfloat16 Kh[KT][72], Kl[KT][72];
    __shared__ __align__(16) __nv_bfloat16 Vh[KT][72], Vl[KT][72];

    int h = blockIdx.y;
    int m0 = (gridDim.x - 1 - blockIdx.x) * 128;   // heavy blocks first
    int tid = threadIdx.x;
    int w = tid >> 5, lane = tid & 31;
    int g = lane >> 2, c = lane & 3;
    int q0w = m0 + w * 16;

    unsigned qh[4][4], ql[4][4];
    {
        const float* Qb = g_Q + ((size_t)h * SEQ + q0w) * HD;
#pragma unroll
        for (int kk = 0; kk < 4; kk++) {
            float2 p0 = *(const float2*)(Qb + (size_t)g * HD + kk * 16 + 2 * c);
            float2 p1 = *(const float2*)(Qb + (size_t)(g + 8) * HD + kk * 16 + 2 * c);
            float2 p2 = *(const float2*)(Qb + (size_t)g * HD + kk * 16 + 2 * c + 8);
            float2 p3 = *(const float2*)(Qb + (size_t)(g + 8) * HD + kk * 16 + 2 * c + 8);
            split_pack(p0.x * 0.125f, p0.y * 0.125f, qh[kk][0], ql[kk][0]);
            split_pack(p1.x * 0.125f, p1.y * 0.125f, qh[kk][1], ql[kk][1]);
            split_pack(p2.x * 0.125f, p2.y * 0.125f, qh[kk][2], ql[kk][2]);
            split_pack(p3.x * 0.125f, p3.y * 0.125f, qh[kk][3], ql[kk][3]);
        }
    }

    int mrow = ((lane >> 4) & 1) * 8 + (lane & 7);
    int mcol = ((lane >> 3) & 1) * 8;
    unsigned kh_base = smem_u32(&Kh[mrow][mcol]);
    unsigned kl_base = smem_u32(&Kl[mrow][mcol]);
    unsigned vh_base = smem_u32(&Vh[lane & 15][(lane >> 4) * 8]);
    unsigned vl_base = smem_u32(&Vl[lane & 15][(lane >> 4) * 8]);

    float o[8][4];
#pragma unroll
    for (int nn = 0; nn < 8; nn++)
#pragma unroll
        for (int i = 0; i < 4; i++) o[nn][i] = 0.f;
    float mrw[2] = {-INFINITY, -INFINITY};
    float lrw[2] = {0.f, 0.f};

    int key = tid >> 3, dg = tid & 7;
    size_t lbase = ((size_t)h * SEQ + key) * (HD / 8) + dg;
    uint4 pkh = g_Kh4[lbase], pkl = g_Kl4[lbase];
    uint4 pvh = g_Vh4[lbase], pvl = g_Vl4[lbase];

    int nT = (m0 + 128) / KT;
    for (int t = 0; t < nT; t++) {
        int kt0 = t * KT;
        __syncthreads();

        *(uint4*)&Kh[key][dg * 8] = pkh;
        *(uint4*)&Kl[key][dg * 8] = pkl;
        *(uint4*)&Vh[key][dg * 8] = pvh;
        *(uint4*)&Vl[key][dg * 8] = pvl;
        __syncthreads();

        if (t + 1 < nT) {
            size_t roff = lbase + (size_t)(kt0 + KT) * (HD / 8);
            pkh = g_Kh4[roff]; pkl = g_Kl4[roff];
            pvh = g_Vh4[roff]; pvl = g_Vl4[roff];
        }

        if (kt0 <= q0w + 15) {
            float s[4][4];
#pragma unroll
            for (int nn = 0; nn < 4; nn++)
#pragma unroll
                for (int i = 0; i < 4; i++) s[nn][i] = 0.f;
#pragma unroll
            for (int kk = 0; kk < 4; kk++) {
#pragma unroll
                for (int q2 = 0; q2 < 2; q2++) {
                    unsigned bh4[4], bl4[4];
                    unsigned off = q2 * (16 * 144) + kk * 32;
                    ldsm_x4(bh4[0], bh4[1], bh4[2], bh4[3], kh_base + off);
                    ldsm_x4(bl4[0], bl4[1], bl4[2], bl4[3], kl_base + off);
                    mma_bf16(s[2 * q2],     qh[kk], bh4);
                    mma_bf16(s[2 * q2],     qh[kk], bl4);
                    mma_bf16(s[2 * q2],     ql[kk], bh4);
                    mma_bf16(s[2 * q2 + 1], qh[kk], bh4 + 2);
                    mma_bf16(s[2 * q2 + 1], qh[kk], bl4 + 2);
                    mma_bf16(s[2 * q2 + 1], ql[kk], bh4 + 2);
                }
            }

            float tmax[2] = {-INFINITY, -INFINITY};
#pragma unroll
            for (int nn = 0; nn < 4; nn++) {
#pragma unroll
                for (int i = 0; i < 4; i++) {
                    int qrow = q0w + g + ((i >> 1) << 3);
                    int kcol = kt0 + nn * 8 + 2 * c + (i & 1);
                    if (kcol > qrow) s[nn][i] = -INFINITY;
                    tmax[i >> 1] = fmaxf(tmax[i >> 1], s[nn][i]);
                }
            }
#pragma unroll
            for (int off = 1; off <= 2; off <<= 1) {
                tmax[0] = fmaxf(tmax[0], __shfl_xor_sync(0xffffffffu, tmax[0], off));
                tmax[1] = fmaxf(tmax[1], __shfl_xor_sync(0xffffffffu, tmax[1], off));
            }
            float mnew0 = fmaxf(mrw[0], tmax[0]);
            float mnew1 = fmaxf(mrw[1], tmax[1]);
            float corr0 = __expf(mrw[0] - mnew0);
            float corr1 = __expf(mrw[1] - mnew1);
            mrw[0] = mnew0; mrw[1] = mnew1;

            float rsum[2] = {0.f, 0.f};
#pragma unroll
            for (int nn = 0; nn < 4; nn++) {
#pragma unroll
                for (int i = 0; i < 4; i++) {
                    float p = __expf(s[nn][i] - ((i >> 1) ? mnew1 : mnew0));
                    s[nn][i] = p;
                    rsum[i >> 1] += p;
                }
            }
#pragma unroll
            for (int off = 1; off <= 2; off <<= 1) {
                rsum[0] += __shfl_xor_sync(0xffffffffu, rsum[0], off);
                rsum[1] += __shfl_xor_sync(0xffffffffu, rsum[1], off);
            }
            lrw[0] = lrw[0] * corr0 + rsum[0];
            lrw[1] = lrw[1] * corr1 + rsum[1];
#pragma unroll
            for (int nn = 0; nn < 8; nn++) {
                o[nn][0] *= corr0; o[nn][1] *= corr0;
                o[nn][2] *= corr1; o[nn][3] *= corr1;
            }

#pragma unroll
            for (int kk = 0; kk < 2; kk++) {
                unsigned ah[4], al[4];
                split_pack(s[2 * kk][0],     s[2 * kk][1],     ah[0], al[0]);
                split_pack(s[2 * kk][2],     s[2 * kk][3],     ah[1], al[1]);
                split_pack(s[2 * kk + 1][0], s[2 * kk + 1][1], ah[2], al[2]);
                split_pack(s[2 * kk + 1][2], s[2 * kk + 1][3], ah[3], al[3]);
#pragma unroll
                for (int np = 0; np < 4; np++) {
                    unsigned bh4[4], bl4[4];
                    unsigned off = kk * (16 * 144) + np * 32;
                    ldsm_x4_trans(bh4[0], bh4[1], bh4[2], bh4[3], vh_base + off);
                    ldsm_x4_trans(bl4[0], bl4[1], bl4[2], bl4[3], vl_base + off);
                    mma_bf16(o[np * 2],     ah, bh4);
                    mma_bf16(o[np * 2],     ah, bl4);
                    mma_bf16(o[np * 2],     al, bh4);
                    mma_bf16(o[np * 2 + 1], ah, bh4 + 2);
                    mma_bf16(o[np * 2 + 1], ah, bl4 + 2);
                    mma_bf16(o[np * 2 + 1], al, bh4 + 2);
                }
            }
        }
    }

    // ---- normalize + write O as pre-split bf16 kpair words ----
    float inv0 = 1.f / lrw[0];
    float inv1 = 1.f / lrw[1];
#pragma unroll
    for (int nn = 0; nn < 8; nn++) {
        int wi0 = (q0w + g) * (DIM / 2) + h * 32 + nn * 4 + c;
        int wi1 = (q0w + g + 8) * (DIM / 2) + h * 32 + nn * 4 + c;
        unsigned h0, l0, h1, l1;
        split_pack(o[nn][0] * inv0, o[nn][1] * inv0, h0, l0);
        split_pack(o[nn][2] * inv1, o[nn][3] * inv1, h1, l1);
        g_Oh[wi0] = h0; g_Ol[wi0] = l0;
        g_Oh[wi1] = h1; g_Ol[wi1] = l1;
    }
}

// ---------------- LayerNorm over last dim (1024) ------------------------
__global__ __launch_bounds__(256)
void layernorm_kernel(const float* __restrict__ gamma,
                      const float* __restrict__ beta,
                      float* __restrict__ Y) {
    int r = blockIdx.x;
    const float* x = g_att + (size_t)r * DIM;
    int tid = threadIdx.x;

    float s = 0.f, s2 = 0.f;
#pragma unroll
    for (int it = 0; it < DIM / 256; it++) {
        float v = x[tid + it * 256];
        s += v;
        s2 += v * v;
    }
#pragma unroll
    for (int off = 16; off; off >>= 1) {
        s  += __shfl_xor_sync(0xffffffffu, s, off);
        s2 += __shfl_xor_sync(0xffffffffu, s2, off);
    }
    __shared__ float ws[8], ws2[8];
    int w = tid >> 5, lane = tid & 31;
    if (lane == 0) { ws[w] = s; ws2[w] = s2; }
    __syncthreads();
    float S1 = 0.f, S2 = 0.f;
#pragma unroll
    for (int i = 0; i < 8; i++) { S1 += ws[i]; S2 += ws2[i]; }

    float mu  = S1 * (1.f / DIM);
    float var = S2 * (1.f / DIM) - mu * mu;
    float inv = rsqrtf(var + 1e-5f);
#pragma unroll
    for (int it = 0; it < DIM / 256; it++) {
        int j = tid + it * 256;
        float v = x[j];
        Y[(size_t)r * DIM + j] = (v - mu) * inv * gamma[j] + beta[j];
    }
}

// ---------------- launch ------------------------------------------------
extern "C" void kernel_launch(void* const* d_in, const int* in_sizes, int n_in,
                              void* d_out, int out_size) {
    const float* x     = (const float*)d_in[0];
    const float* Wqkv  = (const float*)d_in[1];
    const float* bqkv  = (const float*)d_in[2];
    const float* Wo    = (const float*)d_in[3];
    const float* bo    = (const float*)d_in[4];
    const float* gamma = (const float*)d_in[5];
    const float* beta  = (const float*)d_in[6];
    float* out = (float*)d_out;

    unsigned *Wqh, *Wql, *Woh, *Wol;
    cudaGetSymbolAddress((void**)&Wqh, g_Wqh);
    cudaGetSymbolAddress((void**)&Wql, g_Wql);
    cudaGetSymbolAddress((void**)&Woh, g_Woh);
    cudaGetSymbolAddress((void**)&Wol, g_Wol);

    rope_invf_kernel<<<2, 256>>>();
    rope_tables_kernel<<<(SEQ * 512) / 256, 256>>>();
    split_x_kernel<<<(SEQ * 512) / 256, 256>>>(x);
    split_w_kernel<<<(512 * 3 * DIM) / 256, 256>>>(Wqkv, Wqh, Wql, 3 * DIM);
    split_w_kernel<<<(512 * DIM) / 256, 256>>>(Wo, Woh, Wol, DIM);
    gemm_qkv_kernel<<<dim3(3 * DIM / 128, SEQ / 128), 256>>>(bqkv);
    rope_scatter_kernel<<<(SEQ * DIM) / 256, 256>>>();
    flash_bf16_kernel<<<dim3(SEQ / 128, NH), 256>>>();
    gemm_out_kernel<<<dim3(DIM / 128, SEQ / 128), 256>>>(bo);
    layernorm_kernel<<<SEQ, 256>>>(gamma, beta, out);
}

// round 17
// speedup vs baseline: 1.4966x; 1.0224x over previous
#include <cuda_runtime.h>
#include <cuda_bf16.h>
#include <math.h>

#define SEQ 4096
#define DIM 1024
#define NH  16
#define HD  64
#define KT  32   // keys per flash tile

// ---------------- device scratch (no allocation allowed) ----------------
__device__ float g_qkv[SEQ * 3 * DIM];      // QKV projection output (fp32)
__device__ float g_Q[NH * SEQ * HD];        // roped Q, head-major, fp32
__device__ uint4 g_Kh4[NH * SEQ * HD / 8];  // K bf16 hi, head-major
__device__ uint4 g_Kl4[NH * SEQ * HD / 8];  // K bf16 lo
__device__ uint4 g_Vh4[NH * SEQ * HD / 8];  // V bf16 hi
__device__ uint4 g_Vl4[NH * SEQ * HD / 8];  // V bf16 lo
__device__ unsigned g_xh[SEQ * DIM / 2];    // x split, row-major kpair words
__device__ unsigned g_xl[SEQ * DIM / 2];
__device__ unsigned g_Wqh[(DIM / 2) * (3 * DIM)];  // Wqkv split, kpair-packed
__device__ unsigned g_Wql[(DIM / 2) * (3 * DIM)];
__device__ unsigned g_Woh[(DIM / 2) * DIM];        // Wo split, kpair-packed
__device__ unsigned g_Wol[(DIM / 2) * DIM];
__device__ unsigned g_Oh[SEQ * DIM / 2];    // attention out split, row-major
__device__ unsigned g_Ol[SEQ * DIM / 2];
__device__ float g_att[SEQ * DIM];          // after out-proj, pre-LN
__device__ float g_cos[SEQ * 512];
__device__ float g_sin[SEQ * 512];
__device__ float g_invf[512];

// ---------------- BF16 helpers ------------------------------------------
__device__ __forceinline__ void mma_bf16(float* c, const unsigned* a, const unsigned* b) {
    asm volatile(
        "mma.sync.aligned.m16n8k16.row.col.f32.bf16.bf16.f32 "
        "{%0,%1,%2,%3}, {%4,%5,%6,%7}, {%8,%9}, {%0,%1,%2,%3};"
        : "+f"(c[0]), "+f"(c[1]), "+f"(c[2]), "+f"(c[3])
        : "r"(a[0]), "r"(a[1]), "r"(a[2]), "r"(a[3]), "r"(b[0]), "r"(b[1]));
}
__device__ __forceinline__ void split_pack(float a, float b, unsigned& h, unsigned& l) {
    __nv_bfloat16 ah = __float2bfloat16_rn(a);
    __nv_bfloat16 bh = __float2bfloat16_rn(b);
    float ar = a - __bfloat162float(ah);
    float br = b - __bfloat162float(bh);
    __nv_bfloat162 hv; hv.x = ah; hv.y = bh;
    __nv_bfloat162 lv = __floats2bfloat162_rn(ar, br);
    h = *reinterpret_cast<unsigned*>(&hv);
    l = *reinterpret_cast<unsigned*>(&lv);
}
__device__ __forceinline__ float ex2(float x) {   // raw exp2 (input already log2-domain)
    float r;
    asm("ex2.approx.f32 %0, %1;" : "=f"(r) : "f"(x));
    return r;
}
__device__ __forceinline__ void ldsm_x4_trans(unsigned& r0, unsigned& r1,
                                              unsigned& r2, unsigned& r3, unsigned addr) {
    asm volatile("ldmatrix.sync.aligned.m8n8.x4.trans.shared.b16 {%0,%1,%2,%3}, [%4];"
                 : "=r"(r0), "=r"(r1), "=r"(r2), "=r"(r3) : "r"(addr));
}
__device__ __forceinline__ void ldsm_x4(unsigned& r0, unsigned& r1,
                                        unsigned& r2, unsigned& r3, unsigned addr) {
    asm volatile("ldmatrix.sync.aligned.m8n8.x4.shared.b16 {%0,%1,%2,%3}, [%4];"
                 : "=r"(r0), "=r"(r1), "=r"(r2), "=r"(r3) : "r"(addr));
}
__device__ __forceinline__ unsigned smem_u32(const void* p) {
    unsigned a;
    asm("{ .reg .u64 t; cvta.to.shared.u64 t, %1; cvt.u32.u64 %0, t; }" : "=r"(a) : "l"(p));
    return a;
}

// ---------------- operand pre-split kernels ------------------------------
__global__ void split_x_kernel(const float* __restrict__ x) {
    int idx = blockIdx.x * blockDim.x + threadIdx.x;   // SEQ*512
    float2 v = ((const float2*)x)[idx];
    split_pack(v.x, v.y, g_xh[idx], g_xl[idx]);
}
// W: [1024][N] fp32 -> kpair-packed [512][N]: word(kp,n) = {W[2kp][n], W[2kp+1][n]}
__global__ void split_w_kernel(const float* __restrict__ W, unsigned* __restrict__ wh,
                               unsigned* __restrict__ wl, int N) {
    int idx = blockIdx.x * blockDim.x + threadIdx.x;   // 512*N
    int kp = idx / N, n = idx - kp * N;
    float a = W[(size_t)(2 * kp) * N + n];
    float b = W[(size_t)(2 * kp + 1) * N + n];
    split_pack(a, b, wh[idx], wl[idx]);
}

// ---------------- RoPE tables -------------------------------------------
__global__ void rope_invf_kernel() {
    int i = blockIdx.x * blockDim.x + threadIdx.x;
    if (i < 512)
        g_invf[i] = (float)exp(-((double)i) * (9.210340371976184 / 512.0));
}
__global__ void rope_tables_kernel() {
    int idx = blockIdx.x * blockDim.x + threadIdx.x;
    if (idx >= SEQ * 512) return;
    int s = idx >> 9;
    int i = idx & 511;
    float ang = (float)s * g_invf[i];
    double a = (double)ang;
    double k = rint(a * 0.15915494309189535);
    float r = (float)(a - k * 6.283185307179586);
    g_cos[idx] = cosf(r);
    g_sin[idx] = sinf(r);
}

// ---------------- RoPE apply + head-major scatter + bf16 hi/lo split ----
__global__ void rope_scatter_kernel() {
    int idx = blockIdx.x * blockDim.x + threadIdx.x;   // SEQ*DIM threads
    int s = idx >> 10;
    int j = idx & 1023;
    int i = j & 511;
    float c  = g_cos[(s << 9) + i];
    float sn = g_sin[(s << 9) + i];
    const float* row = g_qkv + (size_t)s * (3 * DIM);
    float q = row[j];
    float k = row[DIM + j];
    float v = row[2 * DIM + j];
    float q2, k2;
    if (j < 512) { q2 = -row[j + 512];       k2 = -row[DIM + j + 512]; }
    else         { q2 =  row[j - 512];       k2 =  row[DIM + j - 512]; }
    float qo = q * c + q2 * sn;
    float ko = k * c + k2 * sn;
    int h = j >> 6, d = j & 63;
    int o = ((h * SEQ) + s) * HD + d;
    g_Q[o] = qo;
    __nv_bfloat16 kh = __float2bfloat16_rn(ko);
    ((__nv_bfloat16*)g_Kh4)[o] = kh;
    ((__nv_bfloat16*)g_Kl4)[o] = __float2bfloat16_rn(ko - __bfloat162float(kh));
    __nv_bfloat16 vh = __float2bfloat16_rn(v);
    ((__nv_bfloat16*)g_Vh4)[o] = vh;
    ((__nv_bfloat16*)g_Vl4)[o] = __float2bfloat16_rn(v - __bfloat162float(vh));
}

// ---------------- BF16x3 GEMM on pre-split operands (R10 structure) -----
__device__ __forceinline__
void bf16_gemm_presplit_body(int N,
                             const unsigned* __restrict__ Ah,
                             const unsigned* __restrict__ Al,
                             const unsigned* __restrict__ Bh,
                             const unsigned* __restrict__ Bl,
                             const float* __restrict__ bias,
                             float* __restrict__ C) {
    __shared__ unsigned As_h[128][20], As_l[128][20];
    __shared__ unsigned Bs_h[16][136], Bs_l[16][136];

    const int KW = DIM / 2;   // 512 kpair words per A row
    int tid = threadIdx.x;
    int w = tid >> 5, lane = tid & 31;
    int g = lane >> 2, c = lane & 3;
    int m0 = blockIdx.y * 128, n0 = blockIdx.x * 128;
    int wm = w >> 1, wn = w & 1;

    float acc[2][8][4];
#pragma unroll
    for (int mi = 0; mi < 2; mi++)
#pragma unroll
        for (int ni = 0; ni < 8; ni++)
#pragma unroll
            for (int i = 0; i < 4; i++) acc[mi][ni][i] = 0.f;

    int am = tid >> 1, akp = (tid & 1) * 8;   // A fill: row, kpair offset
    int bkp = tid >> 4, bn8 = (tid & 15) * 8; // B fill: kpair row, n offset
    const unsigned* Agh = Ah + (size_t)(m0 + am) * KW + akp;
    const unsigned* Agl = Al + (size_t)(m0 + am) * KW + akp;
    const unsigned* Bgh = Bh + (size_t)bkp * N + n0 + bn8;
    const unsigned* Bgl = Bl + (size_t)bkp * N + n0 + bn8;

    for (int cc = 0; cc < 32; cc++) {
        const unsigned* agh = Agh + cc * 16;
        const unsigned* agl = Agl + cc * 16;
        uint4 va0 = *(const uint4*)agh;
        uint4 va1 = *(const uint4*)(agh + 4);
        uint4 vb0 = *(const uint4*)agl;
        uint4 vb1 = *(const uint4*)(agl + 4);
        const unsigned* bgh = Bgh + (size_t)cc * 16 * N;
        const unsigned* bgl = Bgl + (size_t)cc * 16 * N;
        uint4 vc0 = *(const uint4*)bgh;
        uint4 vc1 = *(const uint4*)(bgh + 4);
        uint4 vd0 = *(const uint4*)bgl;
        uint4 vd1 = *(const uint4*)(bgl + 4);
        *(uint4*)&As_h[am][akp]     = va0;
        *(uint4*)&As_h[am][akp + 4] = va1;
        *(uint4*)&As_l[am][akp]     = vb0;
        *(uint4*)&As_l[am][akp + 4] = vb1;
        *(uint4*)&Bs_h[bkp][bn8]     = vc0;
        *(uint4*)&Bs_h[bkp][bn8 + 4] = vc1;
        *(uint4*)&Bs_l[bkp][bn8]     = vd0;
        *(uint4*)&Bs_l[bkp][bn8 + 4] = vd1;
        __syncthreads();

#pragma unroll
        for (int kk = 0; kk < 2; kk++) {
            unsigned ah[2][4], al[2][4];
#pragma unroll
            for (int mi = 0; mi < 2; mi++) {
                int rb = wm * 32 + mi * 16;
                ah[mi][0] = As_h[rb + g][kk * 8 + c];
                ah[mi][1] = As_h[rb + g + 8][kk * 8 + c];
                ah[mi][2] = As_h[rb + g][kk * 8 + c + 4];
                ah[mi][3] = As_h[rb + g + 8][kk * 8 + c + 4];
                al[mi][0] = As_l[rb + g][kk * 8 + c];
                al[mi][1] = As_l[rb + g + 8][kk * 8 + c];
                al[mi][2] = As_l[rb + g][kk * 8 + c + 4];
                al[mi][3] = As_l[rb + g + 8][kk * 8 + c + 4];
            }
#pragma unroll
            for (int ni = 0; ni < 8; ni++) {
                int nb = wn * 64 + ni * 8 + g;
                unsigned bh[2], bl[2];
                bh[0] = Bs_h[kk * 8 + c][nb];
                bh[1] = Bs_h[kk * 8 + c + 4][nb];
                bl[0] = Bs_l[kk * 8 + c][nb];
                bl[1] = Bs_l[kk * 8 + c + 4][nb];
#pragma unroll
                for (int mi = 0; mi < 2; mi++) {
                    mma_bf16(acc[mi][ni], ah[mi], bh);
                    mma_bf16(acc[mi][ni], ah[mi], bl);
                    mma_bf16(acc[mi][ni], al[mi], bh);
                }
            }
        }
        __syncthreads();
    }

#pragma unroll
    for (int mi = 0; mi < 2; mi++) {
#pragma unroll
        for (int ni = 0; ni < 8; ni++) {
            int col = n0 + wn * 64 + ni * 8 + 2 * c;
            float2 bb = *(const float2*)(bias + col);
            int row0 = m0 + wm * 32 + mi * 16 + g;
            float2 c0 = make_float2(acc[mi][ni][0] + bb.x, acc[mi][ni][1] + bb.y);
            float2 c1 = make_float2(acc[mi][ni][2] + bb.x, acc[mi][ni][3] + bb.y);
            *(float2*)(C + (size_t)row0 * N + col) = c0;
            *(float2*)(C + (size_t)(row0 + 8) * N + col) = c1;
        }
    }
}

__global__ __launch_bounds__(256, 2)
void gemm_qkv_kernel(const float* __restrict__ bqkv) {
    bf16_gemm_presplit_body(3 * DIM, g_xh, g_xl, g_Wqh, g_Wql, bqkv, g_qkv);
}

__global__ __launch_bounds__(256, 2)
void gemm_out_kernel(const float* __restrict__ bo) {
    bf16_gemm_presplit_body(DIM, g_Oh, g_Ol, g_Woh, g_Wol, bo, g_att);
}

// ---------------- causal flash attention, BF16x3 -------------------------
// Scores carried in log2 domain (Q pre-scaled by 0.125*log2e) -> bare EX2.
// Mask block only for warp-uniformly-diagonal tiles.
__global__ __launch_bounds__(256, 2)
void flash_bf16_kernel() {
    __shared__ __align__(16) __nv_bfloat16 Kh[KT][72], Kl[KT][72];
    __shared__ __align__(16) __nv_bfloat16 Vh[KT][72], Vl[KT][72];

    int h = blockIdx.y;
    int m0 = (gridDim.x - 1 - blockIdx.x) * 128;   // heavy blocks first
    int tid = threadIdx.x;
    int w = tid >> 5, lane = tid & 31;
    int g = lane >> 2, c = lane & 3;
    int q0w = m0 + w * 16;

    const float QSC = 0.125f * 1.44269504088896f;   // 1/sqrt(64) * log2(e)
    unsigned qh[4][4], ql[4][4];
    {
        const float* Qb = g_Q + ((size_t)h * SEQ + q0w) * HD;
#pragma unroll
        for (int kk = 0; kk < 4; kk++) {
            float2 p0 = *(const float2*)(Qb + (size_t)g * HD + kk * 16 + 2 * c);
            float2 p1 = *(const float2*)(Qb + (size_t)(g + 8) * HD + kk * 16 + 2 * c);
            float2 p2 = *(const float2*)(Qb + (size_t)g * HD + kk * 16 + 2 * c + 8);
            float2 p3 = *(const float2*)(Qb + (size_t)(g + 8) * HD + kk * 16 + 2 * c + 8);
            split_pack(p0.x * QSC, p0.y * QSC, qh[kk][0], ql[kk][0]);
            split_pack(p1.x * QSC, p1.y * QSC, qh[kk][1], ql[kk][1]);
            split_pack(p2.x * QSC, p2.y * QSC, qh[kk][2], ql[kk][2]);
            split_pack(p3.x * QSC, p3.y * QSC, qh[kk][3], ql[kk][3]);
        }
    }

    int mrow = ((lane >> 4) & 1) * 8 + (lane & 7);
    int mcol = ((lane >> 3) & 1) * 8;
    unsigned kh_base = smem_u32(&Kh[mrow][mcol]);
    unsigned kl_base = smem_u32(&Kl[mrow][mcol]);
    unsigned vh_base = smem_u32(&Vh[lane & 15][(lane >> 4) * 8]);
    unsigned vl_base = smem_u32(&Vl[lane & 15][(lane >> 4) * 8]);

    float o[8][4];
#pragma unroll
    for (int nn = 0; nn < 8; nn++)
#pragma unroll
        for (int i = 0; i < 4; i++) o[nn][i] = 0.f;
    float mrw[2] = {-INFINITY, -INFINITY};
    float lrw[2] = {0.f, 0.f};

    int key = tid >> 3, dg = tid & 7;
    size_t lbase = ((size_t)h * SEQ + key) * (HD / 8) + dg;
    uint4 pkh = g_Kh4[lbase], pkl = g_Kl4[lbase];
    uint4 pvh = g_Vh4[lbase], pvl = g_Vl4[lbase];

    int nT = (m0 + 128) / KT;
    for (int t = 0; t < nT; t++) {
        int kt0 = t * KT;
        __syncthreads();

        *(uint4*)&Kh[key][dg * 8] = pkh;
        *(uint4*)&Kl[key][dg * 8] = pkl;
        *(uint4*)&Vh[key][dg * 8] = pvh;
        *(uint4*)&Vl[key][dg * 8] = pvl;
        __syncthreads();

        if (t + 1 < nT) {
            size_t roff = lbase + (size_t)(kt0 + KT) * (HD / 8);
            pkh = g_Kh4[roff]; pkl = g_Kl4[roff];
            pvh = g_Vh4[roff]; pvl = g_Vl4[roff];
        }

        if (kt0 <= q0w + 15) {
            float s[4][4];
#pragma unroll
            for (int nn = 0; nn < 4; nn++)
#pragma unroll
                for (int i = 0; i < 4; i++) s[nn][i] = 0.f;
#pragma unroll
            for (int kk = 0; kk < 4; kk++) {
#pragma unroll
                for (int q2 = 0; q2 < 2; q2++) {
                    unsigned bh4[4], bl4[4];
                    unsigned off = q2 * (16 * 144) + kk * 32;
                    ldsm_x4(bh4[0], bh4[1], bh4[2], bh4[3], kh_base + off);
                    ldsm_x4(bl4[0], bl4[1], bl4[2], bl4[3], kl_base + off);
                    mma_bf16(s[2 * q2],     qh[kk], bh4);
                    mma_bf16(s[2 * q2],     qh[kk], bl4);
                    mma_bf16(s[2 * q2],     ql[kk], bh4);
                    mma_bf16(s[2 * q2 + 1], qh[kk], bh4 + 2);
                    mma_bf16(s[2 * q2 + 1], qh[kk], bl4 + 2);
                    mma_bf16(s[2 * q2 + 1], ql[kk], bh4 + 2);
                }
            }

            // causal mask only when this warp's tile straddles the diagonal
            if (kt0 + 31 > q0w) {
#pragma unroll
                for (int nn = 0; nn < 4; nn++) {
#pragma unroll
                    for (int i = 0; i < 4; i++) {
                        int qrow = q0w + g + ((i >> 1) << 3);
                        int kcol = kt0 + nn * 8 + 2 * c + (i & 1);
                        if (kcol > qrow) s[nn][i] = -INFINITY;
                    }
                }
            }

            float tmax[2] = {-INFINITY, -INFINITY};
#pragma unroll
            for (int nn = 0; nn < 4; nn++) {
#pragma unroll
                for (int i = 0; i < 4; i++)
                    tmax[i >> 1] = fmaxf(tmax[i >> 1], s[nn][i]);
            }
#pragma unroll
            for (int off = 1; off <= 2; off <<= 1) {
                tmax[0] = fmaxf(tmax[0], __shfl_xor_sync(0xffffffffu, tmax[0], off));
                tmax[1] = fmaxf(tmax[1], __shfl_xor_sync(0xffffffffu, tmax[1], off));
            }
            float mnew0 = fmaxf(mrw[0], tmax[0]);
            float mnew1 = fmaxf(mrw[1], tmax[1]);
            float corr0 = ex2(mrw[0] - mnew0);
            float corr1 = ex2(mrw[1] - mnew1);
            mrw[0] = mnew0; mrw[1] = mnew1;

            float rsum[2] = {0.f, 0.f};
#pragma unroll
            for (int nn = 0; nn < 4; nn++) {
#pragma unroll
                for (int i = 0; i < 4; i++) {
                    float p = ex2(s[nn][i] - ((i >> 1) ? mnew1 : mnew0));
                    s[nn][i] = p;
                    rsum[i >> 1] += p;
                }
            }
#pragma unroll
            for (int off = 1; off <= 2; off <<= 1) {
                rsum[0] += __shfl_xor_sync(0xffffffffu, rsum[0], off);
                rsum[1] += __shfl_xor_sync(0xffffffffu, rsum[1], off);
            }
            lrw[0] = lrw[0] * corr0 + rsum[0];
            lrw[1] = lrw[1] * corr1 + rsum[1];
#pragma unroll
            for (int nn = 0; nn < 8; nn++) {
                o[nn][0] *= corr0; o[nn][1] *= corr0;
                o[nn][2] *= corr1; o[nn][3] *= corr1;
            }

#pragma unroll
            for (int kk = 0; kk < 2; kk++) {
                unsigned ah[4], al[4];
                split_pack(s[2 * kk][0],     s[2 * kk][1],     ah[0], al[0]);
                split_pack(s[2 * kk][2],     s[2 * kk][3],     ah[1], al[1]);
                split_pack(s[2 * kk + 1][0], s[2 * kk + 1][1], ah[2], al[2]);
                split_pack(s[2 * kk + 1][2], s[2 * kk + 1][3], ah[3], al[3]);
#pragma unroll
                for (int np = 0; np < 4; np++) {
                    unsigned bh4[4], bl4[4];
                    unsigned off = kk * (16 * 144) + np * 32;
                    ldsm_x4_trans(bh4[0], bh4[1], bh4[2], bh4[3], vh_base + off);
                    ldsm_x4_trans(bl4[0], bl4[1], bl4[2], bl4[3], vl_base + off);
                    mma_bf16(o[np * 2],     ah, bh4);
                    mma_bf16(o[np * 2],     ah, bl4);
                    mma_bf16(o[np * 2],     al, bh4);
                    mma_bf16(o[np * 2 + 1], ah, bh4 + 2);
                    mma_bf16(o[np * 2 + 1], ah, bl4 + 2);
                    mma_bf16(o[np * 2 + 1], al, bh4 + 2);
                }
            }
        }
    }

    // ---- normalize + write O as pre-split bf16 kpair words ----
    float inv0 = 1.f / lrw[0];
    float inv1 = 1.f / lrw[1];
#pragma unroll
    for (int nn = 0; nn < 8; nn++) {
        int wi0 = (q0w + g) * (DIM / 2) + h * 32 + nn * 4 + c;
        int wi1 = (q0w + g + 8) * (DIM / 2) + h * 32 + nn * 4 + c;
        unsigned h0, l0, h1, l1;
        split_pack(o[nn][0] * inv0, o[nn][1] * inv0, h0, l0);
        split_pack(o[nn][2] * inv1, o[nn][3] * inv1, h1, l1);
        g_Oh[wi0] = h0; g_Ol[wi0] = l0;
        g_Oh[wi1] = h1; g_Ol[wi1] = l1;
    }
}

// ---------------- LayerNorm over last dim (1024) ------------------------
__global__ __launch_bounds__(256)
void layernorm_kernel(const float* __restrict__ gamma,
                      const float* __restrict__ beta,
                      float* __restrict__ Y) {
    int r = blockIdx.x;
    const float* x = g_att + (size_t)r * DIM;
    int tid = threadIdx.x;

    float s = 0.f, s2 = 0.f;
#pragma unroll
    for (int it = 0; it < DIM / 256; it++) {
        float v = x[tid + it * 256];
        s += v;
        s2 += v * v;
    }
#pragma unroll
    for (int off = 16; off; off >>= 1) {
        s  += __shfl_xor_sync(0xffffffffu, s, off);
        s2 += __shfl_xor_sync(0xffffffffu, s2, off);
    }
    __shared__ float ws[8], ws2[8];
    int w = tid >> 5, lane = tid & 31;
    if (lane == 0) { ws[w] = s; ws2[w] = s2; }
    __syncthreads();
    float S1 = 0.f, S2 = 0.f;
#pragma unroll
    for (int i = 0; i < 8; i++) { S1 += ws[i]; S2 += ws2[i]; }

    float mu  = S1 * (1.f / DIM);
    float var = S2 * (1.f / DIM) - mu * mu;
    float inv = rsqrtf(var + 1e-5f);
#pragma unroll
    for (int it = 0; it < DIM / 256; it++) {
        int j = tid + it * 256;
        float v = x[j];
        Y[(size_t)r * DIM + j] = (v - mu) * inv * gamma[j] + beta[j];
    }
}

// ---------------- launch ------------------------------------------------
extern "C" void kernel_launch(void* const* d_in, const int* in_sizes, int n_in,
                              void* d_out, int out_size) {
    const float* x     = (const float*)d_in[0];
    const float* Wqkv  = (const float*)d_in[1];
    const float* bqkv  = (const float*)d_in[2];
    const float* Wo    = (const float*)d_in[3];
    const float* bo    = (const float*)d_in[4];
    const float* gamma = (const float*)d_in[5];
    const float* beta  = (const float*)d_in[6];
    float* out = (float*)d_out;

    unsigned *Wqh, *Wql, *Woh, *Wol;
    cudaGetSymbolAddress((void**)&Wqh, g_Wqh);
    cudaGetSymbolAddress((void**)&Wql, g_Wql);
    cudaGetSymbolAddress((void**)&Woh, g_Woh);
    cudaGetSymbolAddress((void**)&Wol, g_Wol);

    rope_invf_kernel<<<2, 256>>>();
    rope_tables_kernel<<<(SEQ * 512) / 256, 256>>>();
    split_x_kernel<<<(SEQ * 512) / 256, 256>>>(x);
    split_w_kernel<<<(512 * 3 * DIM) / 256, 256>>>(Wqkv, Wqh, Wql, 3 * DIM);
    split_w_kernel<<<(512 * DIM) / 256, 256>>>(Wo, Woh, Wol, DIM);
    gemm_qkv_kernel<<<dim3(3 * DIM / 128, SEQ / 128), 256>>>(bqkv);
    rope_scatter_kernel<<<(SEQ * DIM) / 256, 256>>>();
    flash_bf16_kernel<<<dim3(SEQ / 128, NH), 256>>>();
    gemm_out_kernel<<<dim3(DIM / 128, SEQ / 128), 256>>>(bo);
    layernorm_kernel<<<SEQ, 256>>>(gamma, beta, out);
}